// round 3
// baseline (speedup 1.0000x reference)
#include <cuda_runtime.h>
#include <math.h>

#define B_   8
#define S_   2048
#define KSEL 8
#define DM   1024
#define DFF  4096
#define NB   16
#define RANK 64
#define TRH  256
#define BS_  (B_ * S_)          // 16384 tokens
#define EPSN 1e-8f
#define RES_SCALE 0.1f

// ---------------- scratch (static device globals; no allocations) -------------
__device__ float g_coefA[B_ * NB];
__device__ float g_coefB[B_ * NB];
__device__ float g_A [B_ * DM * RANK];            // 2 M floats
__device__ float g_Bm[B_ * RANK * DFF];           // 2 M floats
__device__ float g_ts[(size_t)BS_ * DM];          // 16 M floats
__device__ float g_P [(size_t)BS_ * RANK];        // 1 M floats
__device__ float g_U [(size_t)BS_ * TRH];         // 4 M floats
__device__ float g_H [(size_t)BS_ * DFF];         // 64 M floats (256 MB)

// ---------------- sentence coefficients -------------------------------------
// sent_coef_{A,B}[b,i] = (sum_n w[b,n]*coef[idx[b,n],i]) / (sum_n w[b,n] + EPS)
__global__ void coef_kernel(const int* __restrict__ nidx, const float* __restrict__ w,
                            const float* __restrict__ cA, const float* __restrict__ cB,
                            float* __restrict__ outA, float* __restrict__ outB) {
    const int b   = blockIdx.x;
    const int tid = threadIdx.x;          // 256 threads
    const int NK  = S_ * KSEL;            // 16384
    float accA[NB] = {}, accB[NB] = {};
    float ws = 0.f;
    for (int n = tid; n < NK; n += 256) {
        float wv = w[b * NK + n];
        int   id = nidx[b * NK + n];
        ws += wv;
        const float4* pa = (const float4*)(cA + (size_t)id * NB);
        const float4* pb = (const float4*)(cB + (size_t)id * NB);
#pragma unroll
        for (int q = 0; q < 4; q++) {
            float4 va = pa[q], vb = pb[q];
            accA[q*4+0] += wv * va.x; accA[q*4+1] += wv * va.y;
            accA[q*4+2] += wv * va.z; accA[q*4+3] += wv * va.w;
            accB[q*4+0] += wv * vb.x; accB[q*4+1] += wv * vb.y;
            accB[q*4+2] += wv * vb.z; accB[q*4+3] += wv * vb.w;
        }
    }
    __shared__ float sbuf[33][9];
    __shared__ float sfin[33];
    const int lane = tid & 31, wid = tid >> 5;
    auto wred = [](float v) {
#pragma unroll
        for (int o = 16; o > 0; o >>= 1) v += __shfl_down_sync(0xffffffffu, v, o);
        return v;
    };
    float r = wred(ws);
    if (lane == 0) sbuf[0][wid] = r;
#pragma unroll
    for (int i = 0; i < NB; i++) { float v = wred(accA[i]); if (lane == 0) sbuf[1 + i][wid] = v; }
#pragma unroll
    for (int i = 0; i < NB; i++) { float v = wred(accB[i]); if (lane == 0) sbuf[17 + i][wid] = v; }
    __syncthreads();
    if (tid < 33) {
        float s = 0.f;
#pragma unroll
        for (int j = 0; j < 8; j++) s += sbuf[tid][j];
        sfin[tid] = s;
    }
    __syncthreads();
    const float denom = sfin[0] + EPSN;
    if (tid < NB)            outA[b * NB + tid]        = sfin[1 + tid]  / denom;
    else if (tid < 2 * NB)   outB[b * NB + (tid - NB)] = sfin[17 + tid - NB] / denom;
}

// ---------------- A[b,d,r] = sum_i cA[b,i] * basis_A[i,d,r] -------------------
__global__ void build_A_kernel(const float* __restrict__ basisA) {
    int t = blockIdx.x * blockDim.x + threadIdx.x;
    const int total = B_ * DM * (RANK / 4);
    if (t >= total) return;
    int r4 = t & 15;                 // RANK/4 = 16
    int d  = (t >> 4) & (DM - 1);
    int b  = t >> 14;                // 16*1024
    float4 acc = make_float4(0, 0, 0, 0);
#pragma unroll
    for (int i = 0; i < NB; i++) {
        float  c = g_coefA[b * NB + i];
        float4 v = *(const float4*)(basisA + ((size_t)i * DM + d) * RANK + r4 * 4);
        acc.x += c * v.x; acc.y += c * v.y; acc.z += c * v.z; acc.w += c * v.w;
    }
    *(float4*)(g_A + ((size_t)b * DM + d) * RANK + r4 * 4) = acc;
}

// ---------------- Bm[b,r,f] = sum_i cB[b,i] * basis_B[i,r,f] ------------------
__global__ void build_B_kernel(const float* __restrict__ basisB) {
    int t = blockIdx.x * blockDim.x + threadIdx.x;
    const int total = B_ * RANK * (DFF / 4);
    if (t >= total) return;
    int f4 = t & 1023;               // DFF/4 = 1024
    int rr = (t >> 10) & 63;
    int b  = t >> 16;                // 64*1024
    float4 acc = make_float4(0, 0, 0, 0);
#pragma unroll
    for (int i = 0; i < NB; i++) {
        float  c = g_coefB[b * NB + i];
        float4 v = *(const float4*)(basisB + ((size_t)i * RANK + rr) * DFF + f4 * 4);
        acc.x += c * v.x; acc.y += c * v.y; acc.z += c * v.z; acc.w += c * v.w;
    }
    *(float4*)(g_Bm + ((size_t)b * RANK + rr) * DFF + f4 * 4) = acc;
}

// ---------------- token_sig[b,s,d] = sum_k sel[b,s,k,d] * w[b,s,k] ------------
__global__ void token_sig_kernel(const float* __restrict__ sel, const float* __restrict__ w) {
    int t = blockIdx.x * blockDim.x + threadIdx.x;
    const int total = BS_ * (DM / 4);
    if (t >= total) return;
    int d4 = t & 255;
    int bs = t >> 8;
    const float* base = sel + (size_t)bs * KSEL * DM + d4 * 4;
    const float* wp   = w + (size_t)bs * KSEL;
    float4 acc = make_float4(0, 0, 0, 0);
#pragma unroll
    for (int k = 0; k < KSEL; k++) {
        float  wv = wp[k];
        float4 v  = *(const float4*)(base + k * DM);
        acc.x += wv * v.x; acc.y += wv * v.y; acc.z += wv * v.z; acc.w += wv * v.w;
    }
    *(float4*)(g_ts + (size_t)bs * DM + d4 * 4) = acc;
}

// ---------------- generic tiled SGEMM with fused epilogues --------------------
__device__ __forceinline__ float gelu_f(float x) {
    return 0.5f * x * (1.f + erff(x * 0.70710678118654752f));
}

// EPI: 0 = store; 1 = relu(acc+bias); 2 = gelu(C_old) + scale*(acc+bias); 3 = acc+bias
template<int BM, int BN, int BK, int TM, int TN, int EPI>
__global__ void __launch_bounds__((BM / TM) * (BN / TN))
gemm_kernel(const float* __restrict__ A, const float* __restrict__ Bmat,
            float* __restrict__ C,
            int M, int N, int K,
            size_t sA, size_t sB, size_t sC,
            const float* __restrict__ bias, float scale) {
    constexpr int NT = (BM / TM) * (BN / TN);
    __shared__ float As[BK][BM];
    __shared__ float Bs[BK][BN];
    const int tid = threadIdx.x;
    const int tcols = BN / TN;
    const int tx = tid % tcols, ty = tid / tcols;
    const int m0 = blockIdx.y * BM, n0 = blockIdx.x * BN;
    const float* Ab = A + blockIdx.z * sA;
    const float* Bb = Bmat + blockIdx.z * sB;
    float*       Cb = C + blockIdx.z * sC;

    float acc[TM][TN];
#pragma unroll
    for (int i = 0; i < TM; i++)
#pragma unroll
        for (int j = 0; j < TN; j++) acc[i][j] = 0.f;

    for (int k0 = 0; k0 < K; k0 += BK) {
        constexpr int AV = BM * BK / 4;
        for (int v = tid; v < AV; v += NT) {
            int row = v / (BK / 4);
            int c4  = v % (BK / 4);
            float4 val = *(const float4*)(Ab + (size_t)(m0 + row) * K + k0 + c4 * 4);
            As[c4 * 4 + 0][row] = val.x;
            As[c4 * 4 + 1][row] = val.y;
            As[c4 * 4 + 2][row] = val.z;
            As[c4 * 4 + 3][row] = val.w;
        }
        constexpr int BV = BK * BN / 4;
        for (int v = tid; v < BV; v += NT) {
            int row = v / (BN / 4);
            int c4  = v % (BN / 4);
            *(float4*)(&Bs[row][c4 * 4]) =
                *(const float4*)(Bb + (size_t)(k0 + row) * N + n0 + c4 * 4);
        }
        __syncthreads();
#pragma unroll
        for (int kk = 0; kk < BK; kk++) {
            float a[TM], bv[TN];
#pragma unroll
            for (int i = 0; i < TM; i++) a[i] = As[kk][ty * TM + i];
#pragma unroll
            for (int j = 0; j < TN; j++) bv[j] = Bs[kk][tx * TN + j];
#pragma unroll
            for (int i = 0; i < TM; i++)
#pragma unroll
                for (int j = 0; j < TN; j++) acc[i][j] += a[i] * bv[j];
        }
        __syncthreads();
    }

#pragma unroll
    for (int i = 0; i < TM; i++) {
        size_t rowoff = (size_t)(m0 + ty * TM + i) * N + n0 + tx * TN;
#pragma unroll
        for (int j = 0; j < TN; j++) {
            float v = acc[i][j];
            int col = n0 + tx * TN + j;
            if (EPI == 1)      v = fmaxf(v + bias[col], 0.f);
            else if (EPI == 2) v = gelu_f(Cb[rowoff + j]) + scale * (v + bias[col]);
            else if (EPI == 3) v = v + bias[col];
            Cb[rowoff + j] = v;
        }
    }
}

// ---------------- launch -----------------------------------------------------
extern "C" void kernel_launch(void* const* d_in, const int* in_sizes, int n_in,
                              void* d_out, int out_size) {
    (void)in_sizes; (void)n_in; (void)out_size;
    const float* x    = (const float*)d_in[0];
    const float* sel  = (const float*)d_in[1];
    const int*   nidx = (const int*)  d_in[2];
    const float* nw   = (const float*)d_in[3];
    const float* bA   = (const float*)d_in[4];
    const float* bB   = (const float*)d_in[5];
    const float* cA   = (const float*)d_in[6];
    const float* cB   = (const float*)d_in[7];
    const float* w1   = (const float*)d_in[8];
    const float* b1   = (const float*)d_in[9];
    const float* w2   = (const float*)d_in[10];
    const float* b2   = (const float*)d_in[11];
    const float* dw   = (const float*)d_in[12];
    const float* db   = (const float*)d_in[13];
    float* out = (float*)d_out;

    float *pCA, *pCB, *pA, *pBm, *pTs, *pP, *pU, *pH;
    cudaGetSymbolAddress((void**)&pCA, g_coefA);
    cudaGetSymbolAddress((void**)&pCB, g_coefB);
    cudaGetSymbolAddress((void**)&pA,  g_A);
    cudaGetSymbolAddress((void**)&pBm, g_Bm);
    cudaGetSymbolAddress((void**)&pTs, g_ts);
    cudaGetSymbolAddress((void**)&pP,  g_P);
    cudaGetSymbolAddress((void**)&pU,  g_U);
    cudaGetSymbolAddress((void**)&pH,  g_H);

    // 1. sentence coefficients (per batch)
    coef_kernel<<<B_, 256>>>(nidx, nw, cA, cB, pCA, pCB);

    // 2. compose A[b] and Bm[b]
    build_A_kernel<<<(B_ * DM * (RANK / 4) + 255) / 256, 256>>>(bA);
    build_B_kernel<<<(B_ * RANK * (DFF / 4) + 255) / 256, 256>>>(bB);

    // 3. token_sig (512 MB read — memory floor of the problem)
    token_sig_kernel<<<(BS_ * (DM / 4) + 255) / 256, 256>>>(sel, nw);

    // 4. P = x @ A[b]   (batched: M=2048, N=64, K=1024)
    {
        dim3 grid(RANK / 64, S_ / 64, B_);
        gemm_kernel<64, 64, 16, 4, 4, 0><<<grid, 256>>>(
            x, pA, pP, S_, RANK, DM,
            (size_t)S_ * DM, (size_t)DM * RANK, (size_t)S_ * RANK, nullptr, 0.f);
    }
    // 5. U = relu(ts @ w1 + b1)   (M=16384, N=256, K=1024)
    {
        dim3 grid(TRH / 128, BS_ / 128, 1);
        gemm_kernel<128, 128, 16, 8, 8, 1><<<grid, 256>>>(
            pTs, w1, pU, BS_, TRH, DM, 0, 0, 0, b1, 0.f);
    }
    // 6. H = P @ Bm[b]   (batched: M=2048, N=4096, K=64)
    {
        dim3 grid(DFF / 128, S_ / 128, B_);
        gemm_kernel<128, 128, 16, 8, 8, 0><<<grid, 256>>>(
            pP, pBm, pH, S_, DFF, RANK,
            (size_t)S_ * RANK, (size_t)RANK * DFF, (size_t)S_ * DFF, nullptr, 0.f);
    }
    // 7. H = gelu(H) + 0.1*(U @ w2 + b2)   (M=16384, N=4096, K=256)
    {
        dim3 grid(DFF / 128, BS_ / 128, 1);
        gemm_kernel<128, 128, 16, 8, 8, 2><<<grid, 256>>>(
            pU, w2, pH, BS_, DFF, TRH, 0, 0, 0, b2, RES_SCALE);
    }
    // 8. out = H @ down_w + down_b   (M=16384, N=1024, K=4096) — dominant GEMM
    {
        dim3 grid(DM / 128, BS_ / 128, 1);
        gemm_kernel<128, 128, 16, 8, 8, 3><<<grid, 256>>>(
            pH, dw, out, BS_, DM, DFF, 0, 0, 0, db, 0.f);
    }
}

// round 5
// speedup vs baseline: 2.2576x; 2.2576x over previous
#include <cuda_runtime.h>
#include <cuda_bf16.h>
#include <math.h>
#include <stdint.h>

#define B_   8
#define S_   2048
#define KSEL 8
#define DM   1024
#define DFF  4096
#define NB   16
#define RANK 64
#define TRH  256
#define BS_  (B_ * S_)          // 16384 tokens
#define EPSN 1e-8f
#define RES_SCALE 0.1f

// ---------------- scratch (static device globals; no allocations) -------------
__device__ float g_coefA[B_ * NB];
__device__ float g_coefB[B_ * NB];
__device__ float g_A [B_ * DM * RANK];
__device__ float g_Bm[B_ * RANK * DFF];
__device__ float g_P [(size_t)BS_ * RANK];
__device__ float g_H [(size_t)BS_ * DFF];                       // 256 MB fp32 (pre-gelu)
__device__ __nv_bfloat16 g_tshi[(size_t)BS_ * DM];
__device__ __nv_bfloat16 g_tslo[(size_t)BS_ * DM];
__device__ __nv_bfloat16 g_Uhi [(size_t)BS_ * TRH];
__device__ __nv_bfloat16 g_Ulo [(size_t)BS_ * TRH];
__device__ __nv_bfloat16 g_Hhi [(size_t)BS_ * DFF];
__device__ __nv_bfloat16 g_Hlo [(size_t)BS_ * DFF];
__device__ __nv_bfloat16 g_w1Thi[(size_t)TRH * DM];             // w1^T [256][1024]
__device__ __nv_bfloat16 g_w1Tlo[(size_t)TRH * DM];
__device__ __nv_bfloat16 g_w2Thi[(size_t)DFF * TRH];            // w2^T [4096][256]
__device__ __nv_bfloat16 g_w2Tlo[(size_t)DFF * TRH];
__device__ __nv_bfloat16 g_dwThi[(size_t)DM * DFF];             // down_w^T [1024][4096]
__device__ __nv_bfloat16 g_dwTlo[(size_t)DM * DFF];

// ======================= PTX helpers (base sm_80-era features) ===============
__device__ __forceinline__ uint32_t smem_u32(const void* p) {
    uint32_t a;
    asm("{ .reg .u64 t; cvta.to.shared.u64 t, %1; cvt.u32.u64 %0, t; }" : "=r"(a) : "l"(p));
    return a;
}
__device__ __forceinline__ void cp_async16(uint32_t saddr, const void* g) {
    asm volatile("cp.async.cg.shared.global [%0], [%1], 16;" :: "r"(saddr), "l"(g));
}
#define CP_COMMIT() asm volatile("cp.async.commit_group;" ::: "memory")
#define CP_WAIT(n)  asm volatile("cp.async.wait_group %0;" :: "n"(n) : "memory")

__device__ __forceinline__ void ldsm4(uint32_t* r, uint32_t addr) {
    asm volatile("ldmatrix.sync.aligned.m8n8.x4.shared.b16 {%0,%1,%2,%3}, [%4];"
                 : "=r"(r[0]), "=r"(r[1]), "=r"(r[2]), "=r"(r[3]) : "r"(addr));
}
__device__ __forceinline__ void mma16816(float* d, const uint32_t* a, const uint32_t* b) {
    asm volatile("mma.sync.aligned.m16n8k16.row.col.f32.bf16.bf16.f32 "
                 "{%0,%1,%2,%3}, {%4,%5,%6,%7}, {%8,%9}, {%0,%1,%2,%3};"
                 : "+f"(d[0]), "+f"(d[1]), "+f"(d[2]), "+f"(d[3])
                 : "r"(a[0]), "r"(a[1]), "r"(a[2]), "r"(a[3]), "r"(b[0]), "r"(b[1]));
}
// XOR swizzle inside an 8KB tile (128 rows x 64B row): bits[4:5] ^= row bits[1:2]
__device__ __forceinline__ uint32_t swz(uint32_t byte) {
    return byte ^ (((byte >> 7) & 3u) << 4);
}
__device__ __forceinline__ float gelu_f(float x) {
    return 0.5f * x * (1.f + erff(x * 0.70710678118654752f));
}
__device__ __forceinline__ void split_bf16(float v, __nv_bfloat16& h, __nv_bfloat16& l) {
    h = __float2bfloat16(v);
    l = __float2bfloat16(v - __bfloat162float(h));
}

// =========== split-bf16 warp-MMA GEMM:  C[M,N] = (Ahi+Alo) @ (Bhi+Blo)^T =====
// A: [M,K] K-major bf16 hi/lo.  B: [N,K] K-major bf16 hi/lo (i.e. W^T).
// Block 128x128, BK=32, 256 thr (8 warps, 4x2 warp grid, warp tile 32x64).
// EPI: 0 = Cout = acc + bias
//      1 = split(gelu(Cin) + scale*(acc+bias)) -> hi/lo
//      2 = split(relu(acc+bias)) -> hi/lo
#define MBM 128
#define MBN 128
#define MBK 32
#define MMA_STAGE 32768          // 4 tiles x 8KB (Ahi, Alo, Bhi, Blo)
#define MMA_SMEM  (2 * MMA_STAGE)

template<int EPI>
__global__ void __launch_bounds__(256)
mma_gemm_kernel(const __nv_bfloat16* __restrict__ Ahi, const __nv_bfloat16* __restrict__ Alo,
                const __nv_bfloat16* __restrict__ Bhi, const __nv_bfloat16* __restrict__ Blo,
                const float* __restrict__ Cin, float* __restrict__ Cout,
                const float* __restrict__ bias, float scale,
                __nv_bfloat16* __restrict__ hi_out, __nv_bfloat16* __restrict__ lo_out,
                int M, int N, int K)
{
    extern __shared__ char smem[];
    const uint32_t sb = smem_u32(smem);
    const int tid  = threadIdx.x;
    const int wid  = tid >> 5, lane = tid & 31;
    const int wm   = wid >> 1, wn = wid & 1;            // 4 x 2 warp grid
    const int m0   = blockIdx.y * MBM, n0 = blockIdx.x * MBN;

    // ---- per-thread gmem->smem copy slots (2 x 16B per tile per thread) -----
    uint32_t sto[2]; size_t ga[2], gb[2];
#pragma unroll
    for (int i = 0; i < 2; i++) {
        int idx = tid * 2 + i;          // 0..511
        int r = idx >> 2, c = idx & 3;  // row 0..127, 16B-col 0..3
        sto[i] = swz((uint32_t)(r * 64 + c * 16));
        ga[i]  = (size_t)(m0 + r) * K + c * 8;
        gb[i]  = (size_t)(n0 + r) * K + c * 8;
    }

    // ---- per-lane ldmatrix offsets ------------------------------------------
    uint32_t aoff[2][2], boff[4][2];
    {
        int lr = lane & 15, lh = lane >> 4;
#pragma unroll
        for (int mt = 0; mt < 2; mt++)
#pragma unroll
            for (int ks = 0; ks < 2; ks++) {
                int row = wm * 32 + mt * 16 + lr;
                aoff[mt][ks] = swz((uint32_t)(row * 64 + (ks * 2 + lh) * 16));
            }
        int q = lane >> 3, rl = lane & 7;
#pragma unroll
        for (int p = 0; p < 4; p++)
#pragma unroll
            for (int ks = 0; ks < 2; ks++) {
                int n = wn * 64 + p * 16 + ((q >> 1) << 3) + rl;
                boff[p][ks] = swz((uint32_t)(n * 64 + ((q & 1) + ks * 2) * 16));
            }
    }

    float acc[2][8][4];
#pragma unroll
    for (int mt = 0; mt < 2; mt++)
#pragma unroll
        for (int nt = 0; nt < 8; nt++)
#pragma unroll
            for (int j = 0; j < 4; j++) acc[mt][nt][j] = 0.f;

    auto load_stage = [&](int kt, int stg) {
        const uint32_t base = sb + stg * MMA_STAGE;
        const size_t kofs = (size_t)kt * MBK;
#pragma unroll
        for (int i = 0; i < 2; i++) {
            cp_async16(base +         sto[i], Ahi + ga[i] + kofs);
            cp_async16(base +  8192 + sto[i], Alo + ga[i] + kofs);
            cp_async16(base + 16384 + sto[i], Bhi + gb[i] + kofs);
            cp_async16(base + 24576 + sto[i], Blo + gb[i] + kofs);
        }
    };

    const int T = K / MBK;
    load_stage(0, 0);
    CP_COMMIT();

    for (int kt = 0; kt < T; kt++) {
        const int stg = kt & 1;
        if (kt + 1 < T) { load_stage(kt + 1, stg ^ 1); CP_COMMIT(); CP_WAIT(1); }
        else            { CP_WAIT(0); }
        __syncthreads();

        const uint32_t base = sb + stg * MMA_STAGE;
#pragma unroll
        for (int ks = 0; ks < 2; ks++) {
            uint32_t ah[2][4], al[2][4], bh[4][4], bl[4][4];
#pragma unroll
            for (int mt = 0; mt < 2; mt++) {
                ldsm4(ah[mt], base +        aoff[mt][ks]);
                ldsm4(al[mt], base + 8192 + aoff[mt][ks]);
            }
#pragma unroll
            for (int p = 0; p < 4; p++) {
                ldsm4(bh[p], base + 16384 + boff[p][ks]);
                ldsm4(bl[p], base + 24576 + boff[p][ks]);
            }
            // bh[p] = { b0(nt=2p), b1(nt=2p), b0(nt=2p+1), b1(nt=2p+1) }
#pragma unroll
            for (int mt = 0; mt < 2; mt++)
#pragma unroll
                for (int nt = 0; nt < 8; nt++) {
                    const uint32_t* bph = &bh[nt >> 1][(nt & 1) * 2];
                    const uint32_t* bpl = &bl[nt >> 1][(nt & 1) * 2];
                    mma16816(acc[mt][nt], ah[mt], bph);   // hi*hi
                    mma16816(acc[mt][nt], ah[mt], bpl);   // hi*lo
                    mma16816(acc[mt][nt], al[mt], bph);   // lo*hi
                }
        }
        __syncthreads();
    }

    // ---- epilogue ------------------------------------------------------------
    const int lr = lane >> 2, lc = (lane & 3) * 2;
#pragma unroll
    for (int mt = 0; mt < 2; mt++)
#pragma unroll
        for (int nt = 0; nt < 8; nt++) {
            int row = m0 + wm * 32 + mt * 16 + lr;
            int col = n0 + wn * 64 + nt * 8 + lc;
            float b0 = __ldg(bias + col), b1 = __ldg(bias + col + 1);
#pragma unroll
            for (int h = 0; h < 2; h++) {
                int r = row + h * 8;
                size_t o = (size_t)r * N + col;
                float v0 = acc[mt][nt][h * 2 + 0] + b0;
                float v1 = acc[mt][nt][h * 2 + 1] + b1;
                if (EPI == 0) {
                    *(float2*)(Cout + o) = make_float2(v0, v1);
                } else if (EPI == 1) {
                    float2 cold = *(const float2*)(Cin + o);
                    v0 = gelu_f(cold.x) + scale * v0;
                    v1 = gelu_f(cold.y) + scale * v1;
                    __nv_bfloat16 h0, l0, h1, l1;
                    split_bf16(v0, h0, l0); split_bf16(v1, h1, l1);
                    *(__nv_bfloat162*)(hi_out + o) = __nv_bfloat162(h0, h1);
                    *(__nv_bfloat162*)(lo_out + o) = __nv_bfloat162(l0, l1);
                } else {  // EPI == 2
                    v0 = fmaxf(v0, 0.f); v1 = fmaxf(v1, 0.f);
                    __nv_bfloat16 h0, l0, h1, l1;
                    split_bf16(v0, h0, l0); split_bf16(v1, h1, l1);
                    *(__nv_bfloat162*)(hi_out + o) = __nv_bfloat162(h0, h1);
                    *(__nv_bfloat162*)(lo_out + o) = __nv_bfloat162(l0, l1);
                }
            }
        }
}

// ---------------- transpose + bf16 split: out[c][r] = in[r][c] ---------------
__global__ void transpose_split_kernel(const float* __restrict__ in,
                                       __nv_bfloat16* __restrict__ ohi,
                                       __nv_bfloat16* __restrict__ olo,
                                       int R, int C) {
    __shared__ float tile[32][33];
    const int tx = threadIdx.x, ty = threadIdx.y;
    const int c0 = blockIdx.x * 32, r0 = blockIdx.y * 32;
#pragma unroll
    for (int j = 0; j < 32; j += 8)
        tile[ty + j][tx] = in[(size_t)(r0 + ty + j) * C + c0 + tx];
    __syncthreads();
#pragma unroll
    for (int j = 0; j < 32; j += 8) {
        float v = tile[tx][ty + j];                 // in[r0+tx][c0+ty+j]
        size_t o = (size_t)(c0 + ty + j) * R + r0 + tx;
        __nv_bfloat16 h, l; split_bf16(v, h, l);
        ohi[o] = h; olo[o] = l;
    }
}

// ---------------- sentence coefficients -------------------------------------
__global__ void coef_kernel(const int* __restrict__ nidx, const float* __restrict__ w,
                            const float* __restrict__ cA, const float* __restrict__ cB,
                            float* __restrict__ outA, float* __restrict__ outB) {
    const int b   = blockIdx.x;
    const int tid = threadIdx.x;
    const int NK  = S_ * KSEL;
    float accA[NB] = {}, accB[NB] = {};
    float ws = 0.f;
    for (int n = tid; n < NK; n += 256) {
        float wv = w[b * NK + n];
        int   id = nidx[b * NK + n];
        ws += wv;
        const float4* pa = (const float4*)(cA + (size_t)id * NB);
        const float4* pb = (const float4*)(cB + (size_t)id * NB);
#pragma unroll
        for (int q = 0; q < 4; q++) {
            float4 va = pa[q], vb = pb[q];
            accA[q*4+0] += wv * va.x; accA[q*4+1] += wv * va.y;
            accA[q*4+2] += wv * va.z; accA[q*4+3] += wv * va.w;
            accB[q*4+0] += wv * vb.x; accB[q*4+1] += wv * vb.y;
            accB[q*4+2] += wv * vb.z; accB[q*4+3] += wv * vb.w;
        }
    }
    __shared__ float sbuf[33][9];
    __shared__ float sfin[33];
    const int lane = tid & 31, wid = tid >> 5;
    auto wred = [](float v) {
#pragma unroll
        for (int o = 16; o > 0; o >>= 1) v += __shfl_down_sync(0xffffffffu, v, o);
        return v;
    };
    float r = wred(ws);
    if (lane == 0) sbuf[0][wid] = r;
#pragma unroll
    for (int i = 0; i < NB; i++) { float v = wred(accA[i]); if (lane == 0) sbuf[1 + i][wid] = v; }
#pragma unroll
    for (int i = 0; i < NB; i++) { float v = wred(accB[i]); if (lane == 0) sbuf[17 + i][wid] = v; }
    __syncthreads();
    if (tid < 33) {
        float s = 0.f;
#pragma unroll
        for (int j = 0; j < 8; j++) s += sbuf[tid][j];
        sfin[tid] = s;
    }
    __syncthreads();
    const float denom = sfin[0] + EPSN;
    if (tid < NB)            outA[b * NB + tid]        = sfin[1 + tid]  / denom;
    else if (tid < 2 * NB)   outB[b * NB + (tid - NB)] = sfin[17 + tid - NB] / denom;
}

// ---------------- A[b,d,r] = sum_i cA[b,i] * basis_A[i,d,r] -------------------
__global__ void build_A_kernel(const float* __restrict__ basisA) {
    int t = blockIdx.x * blockDim.x + threadIdx.x;
    const int total = B_ * DM * (RANK / 4);
    if (t >= total) return;
    int r4 = t & 15;
    int d  = (t >> 4) & (DM - 1);
    int b  = t >> 14;
    float4 acc = make_float4(0, 0, 0, 0);
#pragma unroll
    for (int i = 0; i < NB; i++) {
        float  c = g_coefA[b * NB + i];
        float4 v = *(const float4*)(basisA + ((size_t)i * DM + d) * RANK + r4 * 4);
        acc.x += c * v.x; acc.y += c * v.y; acc.z += c * v.z; acc.w += c * v.w;
    }
    *(float4*)(g_A + ((size_t)b * DM + d) * RANK + r4 * 4) = acc;
}

// ---------------- Bm[b,r,f] = sum_i cB[b,i] * basis_B[i,r,f] ------------------
__global__ void build_B_kernel(const float* __restrict__ basisB) {
    int t = blockIdx.x * blockDim.x + threadIdx.x;
    const int total = B_ * RANK * (DFF / 4);
    if (t >= total) return;
    int f4 = t & 1023;
    int rr = (t >> 10) & 63;
    int b  = t >> 16;
    float4 acc = make_float4(0, 0, 0, 0);
#pragma unroll
    for (int i = 0; i < NB; i++) {
        float  c = g_coefB[b * NB + i];
        float4 v = *(const float4*)(basisB + ((size_t)i * RANK + rr) * DFF + f4 * 4);
        acc.x += c * v.x; acc.y += c * v.y; acc.z += c * v.z; acc.w += c * v.w;
    }
    *(float4*)(g_Bm + ((size_t)b * RANK + rr) * DFF + f4 * 4) = acc;
}

// -------- token_sig split: ts = sum_k sel*w  ->  bf16 hi/lo -------------------
__global__ void token_sig_kernel(const float* __restrict__ sel, const float* __restrict__ w) {
    int t = blockIdx.x * blockDim.x + threadIdx.x;
    const int total = BS_ * (DM / 4);
    if (t >= total) return;
    int d4 = t & 255;
    int bs = t >> 8;
    const float* base = sel + (size_t)bs * KSEL * DM + d4 * 4;
    const float* wp   = w + (size_t)bs * KSEL;
    float4 acc = make_float4(0, 0, 0, 0);
#pragma unroll
    for (int k = 0; k < KSEL; k++) {
        float  wv = wp[k];
        float4 v  = *(const float4*)(base + k * DM);
        acc.x += wv * v.x; acc.y += wv * v.y; acc.z += wv * v.z; acc.w += wv * v.w;
    }
    union { __nv_bfloat16 b[4]; uint2 u; } ph, pl;
    split_bf16(acc.x, ph.b[0], pl.b[0]);
    split_bf16(acc.y, ph.b[1], pl.b[1]);
    split_bf16(acc.z, ph.b[2], pl.b[2]);
    split_bf16(acc.w, ph.b[3], pl.b[3]);
    size_t o = (size_t)bs * DM + d4 * 4;
    *(uint2*)(g_tshi + o) = ph.u;
    *(uint2*)(g_tslo + o) = pl.u;
}

// ---------------- SIMT SGEMM (for small-K GEMMs 4 and 6) ---------------------
template<int BM, int BN, int BK, int TM, int TN>
__global__ void __launch_bounds__((BM / TM) * (BN / TN))
gemm_kernel(const float* __restrict__ A, const float* __restrict__ Bmat,
            float* __restrict__ C,
            int M, int N, int K,
            size_t sA, size_t sB, size_t sC) {
    constexpr int NT = (BM / TM) * (BN / TN);
    __shared__ float As[BK][BM];
    __shared__ float Bs[BK][BN];
    const int tid = threadIdx.x;
    const int tcols = BN / TN;
    const int tx = tid % tcols, ty = tid / tcols;
    const int m0 = blockIdx.y * BM, n0 = blockIdx.x * BN;
    const float* Ab = A + blockIdx.z * sA;
    const float* Bb = Bmat + blockIdx.z * sB;
    float*       Cb = C + blockIdx.z * sC;

    float acc[TM][TN];
#pragma unroll
    for (int i = 0; i < TM; i++)
#pragma unroll
        for (int j = 0; j < TN; j++) acc[i][j] = 0.f;

    for (int k0 = 0; k0 < K; k0 += BK) {
        constexpr int AV = BM * BK / 4;
        for (int v = tid; v < AV; v += NT) {
            int row = v / (BK / 4);
            int c4  = v % (BK / 4);
            float4 val = *(const float4*)(Ab + (size_t)(m0 + row) * K + k0 + c4 * 4);
            As[c4 * 4 + 0][row] = val.x;
            As[c4 * 4 + 1][row] = val.y;
            As[c4 * 4 + 2][row] = val.z;
            As[c4 * 4 + 3][row] = val.w;
        }
        constexpr int BV = BK * BN / 4;
        for (int v = tid; v < BV; v += NT) {
            int row = v / (BN / 4);
            int c4  = v % (BN / 4);
            *(float4*)(&Bs[row][c4 * 4]) =
                *(const float4*)(Bb + (size_t)(k0 + row) * N + n0 + c4 * 4);
        }
        __syncthreads();
#pragma unroll
        for (int kk = 0; kk < BK; kk++) {
            float a[TM], bv[TN];
#pragma unroll
            for (int i = 0; i < TM; i++) a[i] = As[kk][ty * TM + i];
#pragma unroll
            for (int j = 0; j < TN; j++) bv[j] = Bs[kk][tx * TN + j];
#pragma unroll
            for (int i = 0; i < TM; i++)
#pragma unroll
                for (int j = 0; j < TN; j++) acc[i][j] += a[i] * bv[j];
        }
        __syncthreads();
    }
#pragma unroll
    for (int i = 0; i < TM; i++) {
        size_t rowoff = (size_t)(m0 + ty * TM + i) * N + n0 + tx * TN;
#pragma unroll
        for (int j = 0; j < TN; j++) Cb[rowoff + j] = acc[i][j];
    }
}

// ---------------- launch -----------------------------------------------------
extern "C" void kernel_launch(void* const* d_in, const int* in_sizes, int n_in,
                              void* d_out, int out_size) {
    (void)in_sizes; (void)n_in; (void)out_size;
    const float* x    = (const float*)d_in[0];
    const float* sel  = (const float*)d_in[1];
    const int*   nidx = (const int*)  d_in[2];
    const float* nw   = (const float*)d_in[3];
    const float* bA   = (const float*)d_in[4];
    const float* bB   = (const float*)d_in[5];
    const float* cA   = (const float*)d_in[6];
    const float* cB   = (const float*)d_in[7];
    const float* w1   = (const float*)d_in[8];
    const float* b1   = (const float*)d_in[9];
    const float* w2   = (const float*)d_in[10];
    const float* b2   = (const float*)d_in[11];
    const float* dw   = (const float*)d_in[12];
    const float* db   = (const float*)d_in[13];
    float* out = (float*)d_out;

    float *pCA, *pCB, *pA, *pBm, *pP, *pH;
    __nv_bfloat16 *pTsh, *pTsl, *pUh, *pUl, *pHh, *pHl;
    __nv_bfloat16 *pW1h, *pW1l, *pW2h, *pW2l, *pDWh, *pDWl;
    cudaGetSymbolAddress((void**)&pCA,  g_coefA);
    cudaGetSymbolAddress((void**)&pCB,  g_coefB);
    cudaGetSymbolAddress((void**)&pA,   g_A);
    cudaGetSymbolAddress((void**)&pBm,  g_Bm);
    cudaGetSymbolAddress((void**)&pP,   g_P);
    cudaGetSymbolAddress((void**)&pH,   g_H);
    cudaGetSymbolAddress((void**)&pTsh, g_tshi);
    cudaGetSymbolAddress((void**)&pTsl, g_tslo);
    cudaGetSymbolAddress((void**)&pUh,  g_Uhi);
    cudaGetSymbolAddress((void**)&pUl,  g_Ulo);
    cudaGetSymbolAddress((void**)&pHh,  g_Hhi);
    cudaGetSymbolAddress((void**)&pHl,  g_Hlo);
    cudaGetSymbolAddress((void**)&pW1h, g_w1Thi);
    cudaGetSymbolAddress((void**)&pW1l, g_w1Tlo);
    cudaGetSymbolAddress((void**)&pW2h, g_w2Thi);
    cudaGetSymbolAddress((void**)&pW2l, g_w2Tlo);
    cudaGetSymbolAddress((void**)&pDWh, g_dwThi);
    cudaGetSymbolAddress((void**)&pDWl, g_dwTlo);

    cudaFuncSetAttribute(mma_gemm_kernel<0>, cudaFuncAttributeMaxDynamicSharedMemorySize, MMA_SMEM);
    cudaFuncSetAttribute(mma_gemm_kernel<1>, cudaFuncAttributeMaxDynamicSharedMemorySize, MMA_SMEM);
    cudaFuncSetAttribute(mma_gemm_kernel<2>, cudaFuncAttributeMaxDynamicSharedMemorySize, MMA_SMEM);

    // 1. sentence coefficients
    coef_kernel<<<B_, 256>>>(nidx, nw, cA, cB, pCA, pCB);
    // 2. compose A[b], Bm[b]; transpose+split weights
    build_A_kernel<<<(B_ * DM * (RANK / 4) + 255) / 256, 256>>>(bA);
    build_B_kernel<<<(B_ * RANK * (DFF / 4) + 255) / 256, 256>>>(bB);
    transpose_split_kernel<<<dim3(DM / 32, DFF / 32), dim3(32, 8)>>>(dw, pDWh, pDWl, DFF, DM);
    transpose_split_kernel<<<dim3(DFF / 32, TRH / 32), dim3(32, 8)>>>(w2, pW2h, pW2l, TRH, DFF);
    transpose_split_kernel<<<dim3(TRH / 32, DM / 32), dim3(32, 8)>>>(w1, pW1h, pW1l, DM, TRH);
    // 3. token_sig -> bf16 hi/lo (HBM-bound floor, 512 MB read)
    token_sig_kernel<<<(BS_ * (DM / 4) + 255) / 256, 256>>>(sel, nw);
    // 4. P = x @ A[b]   (SIMT, batched, K=1024 N=64)
    {
        dim3 grid(RANK / 64, S_ / 64, B_);
        gemm_kernel<64, 64, 16, 4, 4><<<grid, 256>>>(
            x, pA, pP, S_, RANK, DM,
            (size_t)S_ * DM, (size_t)DM * RANK, (size_t)S_ * RANK);
    }
    // 5. U = relu(ts @ w1 + b1) -> hi/lo    (MMA, M=16384 N=256 K=1024)
    {
        dim3 grid(TRH / MBN, BS_ / MBM);
        mma_gemm_kernel<2><<<grid, 256, MMA_SMEM>>>(
            pTsh, pTsl, pW1h, pW1l, nullptr, nullptr, b1, 0.f, pUh, pUl,
            BS_, TRH, DM);
    }
    // 6. H = P @ Bm[b]   (SIMT, batched, K=64)
    {
        dim3 grid(DFF / 128, S_ / 128, B_);
        gemm_kernel<128, 128, 16, 8, 8><<<grid, 256>>>(
            pP, pBm, pH, S_, DFF, RANK,
            (size_t)S_ * RANK, (size_t)RANK * DFF, (size_t)S_ * DFF);
    }
    // 7. Hsplit = gelu(H) + 0.1*(U @ w2 + b2)   (MMA, M=16384 N=4096 K=256)
    {
        dim3 grid(DFF / MBN, BS_ / MBM);
        mma_gemm_kernel<1><<<grid, 256, MMA_SMEM>>>(
            pUh, pUl, pW2h, pW2l, pH, nullptr, b2, RES_SCALE, pHh, pHl,
            BS_, DFF, TRH);
    }
    // 8. out = Hsplit @ down_w + db   (MMA, M=16384 N=1024 K=4096 — dominant)
    {
        dim3 grid(DM / MBN, BS_ / MBM);
        mma_gemm_kernel<0><<<grid, 256, MMA_SMEM>>>(
            pHh, pHl, pDWh, pDWl, nullptr, out, db, 0.f, nullptr, nullptr,
            BS_, DM, DFF);
    }
}

// round 6
// speedup vs baseline: 2.4460x; 1.0834x over previous
#include <cuda_runtime.h>
#include <cuda_bf16.h>
#include <math.h>
#include <stdint.h>

#define B_   8
#define S_   2048
#define KSEL 8
#define DM   1024
#define DFF  4096
#define NB   16
#define RANK 64
#define TRH  256
#define BS_  (B_ * S_)          // 16384 tokens
#define EPSN 1e-8f
#define RES_SCALE 0.1f

// ---------------- scratch (static device globals; no allocations) -------------
__device__ float g_coefA[B_ * NB];
__device__ float g_coefB[B_ * NB];
__device__ float g_A [B_ * DM * RANK];                          // fp32, [b][d][r]
__device__ float g_H [(size_t)BS_ * DFF];                       // gelu'd coarse, fp32
__device__ __nv_bfloat16 g_Phi [(size_t)BS_ * RANK];
__device__ __nv_bfloat16 g_Plo [(size_t)BS_ * RANK];
__device__ __nv_bfloat16 g_BmThi[(size_t)B_ * DFF * RANK];      // [b][f][r]
__device__ __nv_bfloat16 g_BmTlo[(size_t)B_ * DFF * RANK];
__device__ __nv_bfloat16 g_tshi[(size_t)BS_ * DM];
__device__ __nv_bfloat16 g_tslo[(size_t)BS_ * DM];
__device__ __nv_bfloat16 g_Uhi [(size_t)BS_ * TRH];
__device__ __nv_bfloat16 g_Ulo [(size_t)BS_ * TRH];
__device__ __nv_bfloat16 g_Hhi [(size_t)BS_ * DFF];
__device__ __nv_bfloat16 g_Hlo [(size_t)BS_ * DFF];
__device__ __nv_bfloat16 g_w1Thi[(size_t)TRH * DM];             // w1^T [256][1024]
__device__ __nv_bfloat16 g_w1Tlo[(size_t)TRH * DM];
__device__ __nv_bfloat16 g_w2Thi[(size_t)DFF * TRH];            // w2^T [4096][256]
__device__ __nv_bfloat16 g_w2Tlo[(size_t)DFF * TRH];
__device__ __nv_bfloat16 g_dwThi[(size_t)DM * DFF];             // down_w^T [1024][4096]
__device__ __nv_bfloat16 g_dwTlo[(size_t)DM * DFF];

// ======================= PTX helpers =========================================
__device__ __forceinline__ uint32_t smem_u32(const void* p) {
    uint32_t a;
    asm("{ .reg .u64 t; cvta.to.shared.u64 t, %1; cvt.u32.u64 %0, t; }" : "=r"(a) : "l"(p));
    return a;
}
__device__ __forceinline__ void cp_async16(uint32_t saddr, const void* g) {
    asm volatile("cp.async.cg.shared.global [%0], [%1], 16;" :: "r"(saddr), "l"(g));
}
#define CP_COMMIT() asm volatile("cp.async.commit_group;" ::: "memory")
#define CP_WAIT(n)  asm volatile("cp.async.wait_group %0;" :: "n"(n) : "memory")

__device__ __forceinline__ void ldsm4(uint32_t* r, uint32_t addr) {
    asm volatile("ldmatrix.sync.aligned.m8n8.x4.shared.b16 {%0,%1,%2,%3}, [%4];"
                 : "=r"(r[0]), "=r"(r[1]), "=r"(r[2]), "=r"(r[3]) : "r"(addr));
}
__device__ __forceinline__ void mma16816(float* d, const uint32_t* a, const uint32_t* b) {
    asm volatile("mma.sync.aligned.m16n8k16.row.col.f32.bf16.bf16.f32 "
                 "{%0,%1,%2,%3}, {%4,%5,%6,%7}, {%8,%9}, {%0,%1,%2,%3};"
                 : "+f"(d[0]), "+f"(d[1]), "+f"(d[2]), "+f"(d[3])
                 : "r"(a[0]), "r"(a[1]), "r"(a[2]), "r"(a[3]), "r"(b[0]), "r"(b[1]));
}
// XOR swizzle inside an 8KB tile (rows x 64B): bits[4:5] ^= row bits[1:2]
__device__ __forceinline__ uint32_t swz(uint32_t byte) {
    return byte ^ (((byte >> 7) & 3u) << 4);
}
__device__ __forceinline__ float gelu_f(float x) {
    return 0.5f * x * (1.f + erff(x * 0.70710678118654752f));
}
__device__ __forceinline__ void split_bf16(float v, __nv_bfloat16& h, __nv_bfloat16& l) {
    h = __float2bfloat16(v);
    l = __float2bfloat16(v - __bfloat162float(h));
}

// =========== split-bf16 warp-MMA GEMM:  C[M,N] = (Ahi+Alo) @ (Bhi+Blo)^T =====
// A: [M,K] K-major bf16 hi/lo.  B: [N,K] K-major bf16 hi/lo.
// Block 128x128, BK=32, 256 thr (8 warps, 4x2 warp grid, warp tile 32x64).
// EPI: 0 = Cout = acc + bias
//      1 = split(Cin + scale*(acc+bias)) -> hi/lo      (Cin already gelu'd)
//      2 = split(relu(acc+bias)) -> hi/lo
//      3 = Cout = gelu(acc)   (no bias)
#define MBM 128
#define MBN 128
#define MBK 32
#define MMA_STAGE 32768
#define MMA_SMEM  (2 * MMA_STAGE)

template<int EPI>
__global__ void __launch_bounds__(256)
mma_gemm_kernel(const __nv_bfloat16* __restrict__ Ahi, const __nv_bfloat16* __restrict__ Alo,
                const __nv_bfloat16* __restrict__ Bhi, const __nv_bfloat16* __restrict__ Blo,
                const float* __restrict__ Cin, float* __restrict__ Cout,
                const float* __restrict__ bias, float scale,
                __nv_bfloat16* __restrict__ hi_out, __nv_bfloat16* __restrict__ lo_out,
                int M, int N, int K,
                size_t sAb, size_t sBb, size_t sCb)
{
    extern __shared__ char smem[];
    const uint32_t sb = smem_u32(smem);
    const int tid  = threadIdx.x;
    const int wid  = tid >> 5, lane = tid & 31;
    const int wm   = wid >> 1, wn = wid & 1;            // 4 x 2 warp grid
    const int m0   = blockIdx.y * MBM, n0 = blockIdx.x * MBN;
    const size_t zA = blockIdx.z * sAb, zB = blockIdx.z * sBb, zC = blockIdx.z * sCb;
    Ahi += zA; Alo += zA; Bhi += zB; Blo += zB;

    uint32_t sto[2]; size_t ga[2], gb[2];
#pragma unroll
    for (int i = 0; i < 2; i++) {
        int idx = tid * 2 + i;          // 0..511
        int r = idx >> 2, c = idx & 3;  // row 0..127, 16B-col 0..3
        sto[i] = swz((uint32_t)(r * 64 + c * 16));
        ga[i]  = (size_t)(m0 + r) * K + c * 8;
        gb[i]  = (size_t)(n0 + r) * K + c * 8;
    }

    uint32_t aoff[2][2], boff[4][2];
    {
        int lr = lane & 15, lh = lane >> 4;
#pragma unroll
        for (int mt = 0; mt < 2; mt++)
#pragma unroll
            for (int ks = 0; ks < 2; ks++) {
                int row = wm * 32 + mt * 16 + lr;
                aoff[mt][ks] = swz((uint32_t)(row * 64 + (ks * 2 + lh) * 16));
            }
        int q = lane >> 3, rl = lane & 7;
#pragma unroll
        for (int p = 0; p < 4; p++)
#pragma unroll
            for (int ks = 0; ks < 2; ks++) {
                int n = wn * 64 + p * 16 + ((q >> 1) << 3) + rl;
                boff[p][ks] = swz((uint32_t)(n * 64 + ((q & 1) + ks * 2) * 16));
            }
    }

    float acc[2][8][4];
#pragma unroll
    for (int mt = 0; mt < 2; mt++)
#pragma unroll
        for (int nt = 0; nt < 8; nt++)
#pragma unroll
            for (int j = 0; j < 4; j++) acc[mt][nt][j] = 0.f;

    auto load_stage = [&](int kt, int stg) {
        const uint32_t base = sb + stg * MMA_STAGE;
        const size_t kofs = (size_t)kt * MBK;
#pragma unroll
        for (int i = 0; i < 2; i++) {
            cp_async16(base +         sto[i], Ahi + ga[i] + kofs);
            cp_async16(base +  8192 + sto[i], Alo + ga[i] + kofs);
            cp_async16(base + 16384 + sto[i], Bhi + gb[i] + kofs);
            cp_async16(base + 24576 + sto[i], Blo + gb[i] + kofs);
        }
    };

    const int T = K / MBK;
    load_stage(0, 0);
    CP_COMMIT();

    for (int kt = 0; kt < T; kt++) {
        const int stg = kt & 1;
        if (kt + 1 < T) { load_stage(kt + 1, stg ^ 1); CP_COMMIT(); CP_WAIT(1); }
        else            { CP_WAIT(0); }
        __syncthreads();

        const uint32_t base = sb + stg * MMA_STAGE;
#pragma unroll
        for (int ks = 0; ks < 2; ks++) {
            uint32_t ah[2][4], al[2][4], bh[4][4], bl[4][4];
#pragma unroll
            for (int mt = 0; mt < 2; mt++) {
                ldsm4(ah[mt], base +        aoff[mt][ks]);
                ldsm4(al[mt], base + 8192 + aoff[mt][ks]);
            }
#pragma unroll
            for (int p = 0; p < 4; p++) {
                ldsm4(bh[p], base + 16384 + boff[p][ks]);
                ldsm4(bl[p], base + 24576 + boff[p][ks]);
            }
#pragma unroll
            for (int mt = 0; mt < 2; mt++)
#pragma unroll
                for (int nt = 0; nt < 8; nt++) {
                    const uint32_t* bph = &bh[nt >> 1][(nt & 1) * 2];
                    const uint32_t* bpl = &bl[nt >> 1][(nt & 1) * 2];
                    mma16816(acc[mt][nt], ah[mt], bph);   // hi*hi
                    mma16816(acc[mt][nt], ah[mt], bpl);   // hi*lo
                    mma16816(acc[mt][nt], al[mt], bph);   // lo*hi
                }
        }
        __syncthreads();
    }

    // ---- epilogue ------------------------------------------------------------
    const int lr = lane >> 2, lc = (lane & 3) * 2;
#pragma unroll
    for (int mt = 0; mt < 2; mt++)
#pragma unroll
        for (int nt = 0; nt < 8; nt++) {
            int row = m0 + wm * 32 + mt * 16 + lr;
            int col = n0 + wn * 64 + nt * 8 + lc;
            float b0 = 0.f, b1 = 0.f;
            if (EPI != 3) { b0 = __ldg(bias + col); b1 = __ldg(bias + col + 1); }
#pragma unroll
            for (int h = 0; h < 2; h++) {
                int r = row + h * 8;
                size_t o = zC + (size_t)r * N + col;
                float v0 = acc[mt][nt][h * 2 + 0] + b0;
                float v1 = acc[mt][nt][h * 2 + 1] + b1;
                if (EPI == 0) {
                    *(float2*)(Cout + o) = make_float2(v0, v1);
                } else if (EPI == 3) {
                    *(float2*)(Cout + o) = make_float2(gelu_f(v0), gelu_f(v1));
                } else {
                    if (EPI == 1) {
                        float2 cold = *(const float2*)(Cin + o);
                        v0 = cold.x + scale * v0;
                        v1 = cold.y + scale * v1;
                    } else {  // EPI == 2
                        v0 = fmaxf(v0, 0.f); v1 = fmaxf(v1, 0.f);
                    }
                    __nv_bfloat16 h0, l0, h1, l1;
                    split_bf16(v0, h0, l0); split_bf16(v1, h1, l1);
                    *(__nv_bfloat162*)(hi_out + o) = __nv_bfloat162(h0, h1);
                    *(__nv_bfloat162*)(lo_out + o) = __nv_bfloat162(l0, l1);
                }
            }
        }
}

// ---------------- sentence coefficients -------------------------------------
__global__ void coef_kernel(const int* __restrict__ nidx, const float* __restrict__ w,
                            const float* __restrict__ cA, const float* __restrict__ cB,
                            float* __restrict__ outA, float* __restrict__ outB) {
    const int b   = blockIdx.x;
    const int tid = threadIdx.x;
    const int NK  = S_ * KSEL;
    float accA[NB] = {}, accB[NB] = {};
    float ws = 0.f;
    for (int n = tid; n < NK; n += 256) {
        float wv = w[b * NK + n];
        int   id = nidx[b * NK + n];
        ws += wv;
        const float4* pa = (const float4*)(cA + (size_t)id * NB);
        const float4* pb = (const float4*)(cB + (size_t)id * NB);
#pragma unroll
        for (int q = 0; q < 4; q++) {
            float4 va = pa[q], vb = pb[q];
            accA[q*4+0] += wv * va.x; accA[q*4+1] += wv * va.y;
            accA[q*4+2] += wv * va.z; accA[q*4+3] += wv * va.w;
            accB[q*4+0] += wv * vb.x; accB[q*4+1] += wv * vb.y;
            accB[q*4+2] += wv * vb.z; accB[q*4+3] += wv * vb.w;
        }
    }
    __shared__ float sbuf[33][9];
    __shared__ float sfin[33];
    const int lane = tid & 31, wid = tid >> 5;
    auto wred = [](float v) {
#pragma unroll
        for (int o = 16; o > 0; o >>= 1) v += __shfl_down_sync(0xffffffffu, v, o);
        return v;
    };
    float r = wred(ws);
    if (lane == 0) sbuf[0][wid] = r;
#pragma unroll
    for (int i = 0; i < NB; i++) { float v = wred(accA[i]); if (lane == 0) sbuf[1 + i][wid] = v; }
#pragma unroll
    for (int i = 0; i < NB; i++) { float v = wred(accB[i]); if (lane == 0) sbuf[17 + i][wid] = v; }
    __syncthreads();
    if (tid < 33) {
        float s = 0.f;
#pragma unroll
        for (int j = 0; j < 8; j++) s += sbuf[tid][j];
        sfin[tid] = s;
    }
    __syncthreads();
    const float denom = sfin[0] + EPSN;
    if (tid < NB)            outA[b * NB + tid]        = sfin[1 + tid]  / denom;
    else if (tid < 2 * NB)   outB[b * NB + (tid - NB)] = sfin[17 + tid - NB] / denom;
}

// ================= merged prep kernel (grid-range dispatch) ==================
// ranges (256 threads each):
//   [0, 16384)                : token_sig -> ts hi/lo
//   [16384, 16896)            : build_A (fp32, [b][d][r])
//   [16896, 17408)            : build BmT hi/lo ([b][f][r]) from basis_B + coefB
//   [17408, 21504)            : transpose+split down_w  -> dwT
//   [21504, 22528)            : transpose+split w2      -> w2T
//   [22528, 22784)            : transpose+split w1      -> w1T
#define PR_TS0   0
#define PR_BA0   16384
#define PR_BBT0  16896
#define PR_TDW0  17408
#define PR_TW20  21504
#define PR_TW10  22528
#define PR_END   22784

__device__ __forceinline__ void prep_transpose(const float* __restrict__ in,
                                               __nv_bfloat16* __restrict__ ohi,
                                               __nv_bfloat16* __restrict__ olo,
                                               int R, int C, int gx, int gy,
                                               float* tile /*[32][33]*/) {
    const int tid = threadIdx.x;
    const int tx = tid & 31, ty = tid >> 5;     // ty 0..7
    const int c0 = gx * 32, r0 = gy * 32;
#pragma unroll
    for (int j = 0; j < 32; j += 8)
        tile[(ty + j) * 33 + tx] = in[(size_t)(r0 + ty + j) * C + c0 + tx];
    __syncthreads();
#pragma unroll
    for (int j = 0; j < 32; j += 8) {
        float v = tile[tx * 33 + ty + j];
        size_t o = (size_t)(c0 + ty + j) * R + r0 + tx;
        __nv_bfloat16 h, l; split_bf16(v, h, l);
        ohi[o] = h; olo[o] = l;
    }
}

__global__ void __launch_bounds__(256)
prep_kernel(const float* __restrict__ sel, const float* __restrict__ w,
            const float* __restrict__ basisA, const float* __restrict__ basisB,
            const float* __restrict__ w1, const float* __restrict__ w2,
            const float* __restrict__ dw) {
    __shared__ float tile[64 * 65];
    const int blk = blockIdx.x;
    const int tid = threadIdx.x;

    if (blk < PR_BA0) {
        // ---- token_sig ----
        int t = blk * 256 + tid;
        int d4 = t & 255;
        int bs = t >> 8;
        const float* base = sel + (size_t)bs * KSEL * DM + d4 * 4;
        const float* wp   = w + (size_t)bs * KSEL;
        float4 acc = make_float4(0, 0, 0, 0);
#pragma unroll
        for (int k = 0; k < KSEL; k++) {
            float  wv = wp[k];
            float4 v  = *(const float4*)(base + k * DM);
            acc.x += wv * v.x; acc.y += wv * v.y; acc.z += wv * v.z; acc.w += wv * v.w;
        }
        union { __nv_bfloat16 b[4]; uint2 u; } ph, pl;
        split_bf16(acc.x, ph.b[0], pl.b[0]);
        split_bf16(acc.y, ph.b[1], pl.b[1]);
        split_bf16(acc.z, ph.b[2], pl.b[2]);
        split_bf16(acc.w, ph.b[3], pl.b[3]);
        size_t o = (size_t)bs * DM + d4 * 4;
        *(uint2*)(g_tshi + o) = ph.u;
        *(uint2*)(g_tslo + o) = pl.u;
    } else if (blk < PR_BBT0) {
        // ---- build_A (fp32) ----
        int t = (blk - PR_BA0) * 256 + tid;
        int r4 = t & 15;
        int d  = (t >> 4) & (DM - 1);
        int b  = t >> 14;
        float4 acc = make_float4(0, 0, 0, 0);
#pragma unroll
        for (int i = 0; i < NB; i++) {
            float  c = g_coefA[b * NB + i];
            float4 v = *(const float4*)(basisA + ((size_t)i * DM + d) * RANK + r4 * 4);
            acc.x += c * v.x; acc.y += c * v.y; acc.z += c * v.z; acc.w += c * v.w;
        }
        *(float4*)(g_A + ((size_t)b * DM + d) * RANK + r4 * 4) = acc;
    } else if (blk < PR_TDW0) {
        // ---- build BmT hi/lo: out[b][f][r] = sum_i cB[b,i]*basis_B[i][r][f] ----
        int lb = blk - PR_BBT0;            // 0..511
        int f0 = (lb & 63) * 64;
        int b  = lb >> 6;
        int r  = tid >> 2;                 // 0..63
        int fq = tid & 3;                  // 16-col chunk
        float accv[16];
#pragma unroll
        for (int j = 0; j < 16; j++) accv[j] = 0.f;
#pragma unroll
        for (int i = 0; i < NB; i++) {
            float c = g_coefB[b * NB + i];
            const float* src = basisB + ((size_t)i * RANK + r) * DFF + f0 + fq * 16;
#pragma unroll
            for (int q = 0; q < 4; q++) {
                float4 v = *(const float4*)(src + q * 4);
                accv[q*4+0] += c * v.x; accv[q*4+1] += c * v.y;
                accv[q*4+2] += c * v.z; accv[q*4+3] += c * v.w;
            }
        }
#pragma unroll
        for (int j = 0; j < 16; j++) tile[r * 65 + fq * 16 + j] = accv[j];
        __syncthreads();
        // write transposed: f rows (64), r contiguous
        int f  = tid >> 2;                 // 0..63
        int rq = tid & 3;
        size_t obase = ((size_t)b * DFF + f0 + f) * RANK + rq * 16;
        __nv_bfloat16 hv[16], lv[16];
#pragma unroll
        for (int j = 0; j < 16; j++) {
            float v = tile[(rq * 16 + j) * 65 + f];
            split_bf16(v, hv[j], lv[j]);
        }
#pragma unroll
        for (int j = 0; j < 16; j += 8) {
            *(uint4*)(g_BmThi + obase + j) = *(uint4*)(hv + j);
            *(uint4*)(g_BmTlo + obase + j) = *(uint4*)(lv + j);
        }
    } else if (blk < PR_TW20) {
        int lb = blk - PR_TDW0;            // dw: R=DFF, C=DM, grid (32 x 128)
        prep_transpose(dw, g_dwThi, g_dwTlo, DFF, DM, lb & 31, lb >> 5, tile);
    } else if (blk < PR_TW10) {
        int lb = blk - PR_TW20;            // w2: R=TRH, C=DFF, grid (128 x 8)
        prep_transpose(w2, g_w2Thi, g_w2Tlo, TRH, DFF, lb & 127, lb >> 7, tile);
    } else {
        int lb = blk - PR_TW10;            // w1: R=DM, C=TRH, grid (8 x 32)
        prep_transpose(w1, g_w1Thi, g_w1Tlo, DM, TRH, lb & 7, lb >> 3, tile);
    }
}

// ---------------- GEMM4: P = x @ A[b]  (SIMT, split epilogue) -----------------
// A operand x: [b][S_][DM]; B operand g_A: [b][DM][RANK]; out P hi/lo [BS_][RANK]
__global__ void __launch_bounds__(256)
gemm4_kernel(const float* __restrict__ x) {
    constexpr int BM = 64, BN = 64, BK = 16, TM = 4, TN = 4;
    __shared__ float As[BK][BM];
    __shared__ float Bs[BK][BN];
    const int tid = threadIdx.x;
    const int tx = tid & 15, ty = tid >> 4;
    const int m0 = blockIdx.y * BM;
    const int z  = blockIdx.z;
    const float* Ab = x + (size_t)z * S_ * DM;
    const float* Bb = g_A + (size_t)z * DM * RANK;

    float acc[TM][TN];
#pragma unroll
    for (int i = 0; i < TM; i++)
#pragma unroll
        for (int j = 0; j < TN; j++) acc[i][j] = 0.f;

    for (int k0 = 0; k0 < DM; k0 += BK) {
        for (int v = tid; v < BM * BK / 4; v += 256) {
            int row = v >> 2, c4 = v & 3;
            float4 val = *(const float4*)(Ab + (size_t)(m0 + row) * DM + k0 + c4 * 4);
            As[c4 * 4 + 0][row] = val.x;
            As[c4 * 4 + 1][row] = val.y;
            As[c4 * 4 + 2][row] = val.z;
            As[c4 * 4 + 3][row] = val.w;
        }
        for (int v = tid; v < BK * BN / 4; v += 256) {
            int row = v >> 4, c4 = v & 15;
            *(float4*)(&Bs[row][c4 * 4]) =
                *(const float4*)(Bb + (size_t)(k0 + row) * RANK + c4 * 4);
        }
        __syncthreads();
#pragma unroll
        for (int kk = 0; kk < BK; kk++) {
            float a[TM], bv[TN];
#pragma unroll
            for (int i = 0; i < TM; i++) a[i] = As[kk][ty * TM + i];
#pragma unroll
            for (int j = 0; j < TN; j++) bv[j] = Bs[kk][tx * TN + j];
#pragma unroll
            for (int i = 0; i < TM; i++)
#pragma unroll
                for (int j = 0; j < TN; j++) acc[i][j] += a[i] * bv[j];
        }
        __syncthreads();
    }
#pragma unroll
    for (int i = 0; i < TM; i++) {
        size_t o = ((size_t)z * S_ + m0 + ty * TM + i) * RANK + tx * TN;
        __nv_bfloat16 hv[TN], lv[TN];
#pragma unroll
        for (int j = 0; j < TN; j++) split_bf16(acc[i][j], hv[j], lv[j]);
        *(uint2*)(g_Phi + o) = *(uint2*)hv;
        *(uint2*)(g_Plo + o) = *(uint2*)lv;
    }
}

// ---------------- launch -----------------------------------------------------
extern "C" void kernel_launch(void* const* d_in, const int* in_sizes, int n_in,
                              void* d_out, int out_size) {
    (void)in_sizes; (void)n_in; (void)out_size;
    const float* x    = (const float*)d_in[0];
    const float* sel  = (const float*)d_in[1];
    const int*   nidx = (const int*)  d_in[2];
    const float* nw   = (const float*)d_in[3];
    const float* bA   = (const float*)d_in[4];
    const float* bB   = (const float*)d_in[5];
    const float* cA   = (const float*)d_in[6];
    const float* cB   = (const float*)d_in[7];
    const float* w1   = (const float*)d_in[8];
    const float* b1   = (const float*)d_in[9];
    const float* w2   = (const float*)d_in[10];
    const float* b2   = (const float*)d_in[11];
    const float* dw   = (const float*)d_in[12];
    const float* db   = (const float*)d_in[13];
    float* out = (float*)d_out;

    float *pCA, *pCB, *pH;
    __nv_bfloat16 *pPh, *pPl, *pBmh, *pBml, *pTsh, *pTsl, *pUh, *pUl, *pHh, *pHl;
    __nv_bfloat16 *pW1h, *pW1l, *pW2h, *pW2l, *pDWh, *pDWl;
    cudaGetSymbolAddress((void**)&pCA,  g_coefA);
    cudaGetSymbolAddress((void**)&pCB,  g_coefB);
    cudaGetSymbolAddress((void**)&pH,   g_H);
    cudaGetSymbolAddress((void**)&pPh,  g_Phi);
    cudaGetSymbolAddress((void**)&pPl,  g_Plo);
    cudaGetSymbolAddress((void**)&pBmh, g_BmThi);
    cudaGetSymbolAddress((void**)&pBml, g_BmTlo);
    cudaGetSymbolAddress((void**)&pTsh, g_tshi);
    cudaGetSymbolAddress((void**)&pTsl, g_tslo);
    cudaGetSymbolAddress((void**)&pUh,  g_Uhi);
    cudaGetSymbolAddress((void**)&pUl,  g_Ulo);
    cudaGetSymbolAddress((void**)&pHh,  g_Hhi);
    cudaGetSymbolAddress((void**)&pHl,  g_Hlo);
    cudaGetSymbolAddress((void**)&pW1h, g_w1Thi);
    cudaGetSymbolAddress((void**)&pW1l, g_w1Tlo);
    cudaGetSymbolAddress((void**)&pW2h, g_w2Thi);
    cudaGetSymbolAddress((void**)&pW2l, g_w2Tlo);
    cudaGetSymbolAddress((void**)&pDWh, g_dwThi);
    cudaGetSymbolAddress((void**)&pDWl, g_dwTlo);

    cudaFuncSetAttribute(mma_gemm_kernel<0>, cudaFuncAttributeMaxDynamicSharedMemorySize, MMA_SMEM);
    cudaFuncSetAttribute(mma_gemm_kernel<1>, cudaFuncAttributeMaxDynamicSharedMemorySize, MMA_SMEM);
    cudaFuncSetAttribute(mma_gemm_kernel<2>, cudaFuncAttributeMaxDynamicSharedMemorySize, MMA_SMEM);
    cudaFuncSetAttribute(mma_gemm_kernel<3>, cudaFuncAttributeMaxDynamicSharedMemorySize, MMA_SMEM);

    // 1. sentence coefficients
    coef_kernel<<<B_, 256>>>(nidx, nw, cA, cB, pCA, pCB);
    // 2. prep: token_sig + build_A + build_BmT + 3 weight transposes
    prep_kernel<<<PR_END, 256>>>(sel, nw, bA, bB, w1, w2, dw);
    // 3. U = relu(ts @ w1 + b1) -> hi/lo    (MMA, M=16384 N=256 K=1024)
    {
        dim3 grid(TRH / MBN, BS_ / MBM);
        mma_gemm_kernel<2><<<grid, 256, MMA_SMEM>>>(
            pTsh, pTsl, pW1h, pW1l, nullptr, nullptr, b1, 0.f, pUh, pUl,
            BS_, TRH, DM, 0, 0, 0);
    }
    // 4. P = x @ A[b]  (SIMT, split epilogue)
    {
        dim3 grid(1, S_ / 64, B_);
        gemm4_kernel<<<grid, 256>>>(x);
    }
    // 5. H = gelu(P @ BmT[b])  (MMA, batched, M=2048/b N=4096 K=64)
    {
        dim3 grid(DFF / MBN, S_ / MBM, B_);
        mma_gemm_kernel<3><<<grid, 256, MMA_SMEM>>>(
            pPh, pPl, pBmh, pBml, nullptr, pH, nullptr, 0.f, nullptr, nullptr,
            S_, DFF, RANK,
            (size_t)S_ * RANK, (size_t)DFF * RANK, (size_t)S_ * DFF);
    }
    // 6. Hsplit = H + 0.1*(U @ w2 + b2)  (MMA, M=16384 N=4096 K=256) — PROFILED
    {
        dim3 grid(DFF / MBN, BS_ / MBM);
        mma_gemm_kernel<1><<<grid, 256, MMA_SMEM>>>(
            pUh, pUl, pW2h, pW2l, pH, nullptr, b2, RES_SCALE, pHh, pHl,
            BS_, DFF, TRH, 0, 0, 0);
    }
    // 7. out = Hsplit @ down_w + db  (MMA, M=16384 N=1024 K=4096 — dominant)
    {
        dim3 grid(DM / MBN, BS_ / MBM);
        mma_gemm_kernel<0><<<grid, 256, MMA_SMEM>>>(
            pHh, pHl, pDWh, pDWl, nullptr, out, db, 0.f, nullptr, nullptr,
            BS_, DM, DFF, 0, 0, 0);
    }
}

// round 7
// speedup vs baseline: 3.5380x; 1.4465x over previous
#include <cuda_runtime.h>
#include <cuda_bf16.h>
#include <math.h>
#include <stdint.h>

#define B_   8
#define S_   2048
#define KSEL 8
#define DM   1024
#define DFF  4096
#define NB   16
#define RANK 64
#define TRH  256
#define BS_  (B_ * S_)          // 16384 tokens
#define EPSN 1e-8f
#define RES_SCALE 0.1f

// ---------------- scratch (static device globals; no allocations) -------------
__device__ float g_coefA[B_ * NB];
__device__ float g_coefB[B_ * NB];
__device__ __nv_bfloat16 g_xhi [(size_t)BS_ * DM];
__device__ __nv_bfloat16 g_xlo [(size_t)BS_ * DM];
__device__ __nv_bfloat16 g_AThi[(size_t)B_ * RANK * DM];        // [b][r][d]
__device__ __nv_bfloat16 g_ATlo[(size_t)B_ * RANK * DM];
__device__ __nv_bfloat16 g_Phi [(size_t)BS_ * RANK];
__device__ __nv_bfloat16 g_Plo [(size_t)BS_ * RANK];
__device__ __nv_bfloat16 g_BmThi[(size_t)B_ * DFF * RANK];      // [b][f][r]
__device__ __nv_bfloat16 g_BmTlo[(size_t)B_ * DFF * RANK];
__device__ __nv_bfloat16 g_tshi[(size_t)BS_ * DM];
__device__ __nv_bfloat16 g_tslo[(size_t)BS_ * DM];
__device__ __nv_bfloat16 g_Uhi [(size_t)BS_ * TRH];
__device__ __nv_bfloat16 g_Ulo [(size_t)BS_ * TRH];
__device__ __nv_bfloat16 g_Hhi [(size_t)BS_ * DFF];
__device__ __nv_bfloat16 g_Hlo [(size_t)BS_ * DFF];
__device__ __nv_bfloat16 g_w1Thi[(size_t)TRH * DM];             // w1^T [256][1024]
__device__ __nv_bfloat16 g_w1Tlo[(size_t)TRH * DM];
__device__ __nv_bfloat16 g_w2Thi[(size_t)DFF * TRH];            // w2^T [4096][256]
__device__ __nv_bfloat16 g_w2Tlo[(size_t)DFF * TRH];
__device__ __nv_bfloat16 g_dwThi[(size_t)DM * DFF];             // down_w^T [1024][4096]
__device__ __nv_bfloat16 g_dwTlo[(size_t)DM * DFF];

// ======================= PTX helpers =========================================
__device__ __forceinline__ uint32_t smem_u32(const void* p) {
    uint32_t a;
    asm("{ .reg .u64 t; cvta.to.shared.u64 t, %1; cvt.u32.u64 %0, t; }" : "=r"(a) : "l"(p));
    return a;
}
__device__ __forceinline__ void cp_async16(uint32_t saddr, const void* g) {
    asm volatile("cp.async.cg.shared.global [%0], [%1], 16;" :: "r"(saddr), "l"(g));
}
#define CP_COMMIT() asm volatile("cp.async.commit_group;" ::: "memory")
#define CP_WAIT(n)  asm volatile("cp.async.wait_group %0;" :: "n"(n) : "memory")

__device__ __forceinline__ void ldsm4(uint32_t* r, uint32_t addr) {
    asm volatile("ldmatrix.sync.aligned.m8n8.x4.shared.b16 {%0,%1,%2,%3}, [%4];"
                 : "=r"(r[0]), "=r"(r[1]), "=r"(r[2]), "=r"(r[3]) : "r"(addr));
}
__device__ __forceinline__ void mma16816(float* d, const uint32_t* a, const uint32_t* b) {
    asm volatile("mma.sync.aligned.m16n8k16.row.col.f32.bf16.bf16.f32 "
                 "{%0,%1,%2,%3}, {%4,%5,%6,%7}, {%8,%9}, {%0,%1,%2,%3};"
                 : "+f"(d[0]), "+f"(d[1]), "+f"(d[2]), "+f"(d[3])
                 : "r"(a[0]), "r"(a[1]), "r"(a[2]), "r"(a[3]), "r"(b[0]), "r"(b[1]));
}
// XOR swizzle inside a tile of 64B rows: bits[4:5] ^= row bits[1:2]
__device__ __forceinline__ uint32_t swz(uint32_t byte) {
    return byte ^ (((byte >> 7) & 3u) << 4);
}
__device__ __forceinline__ float gelu_f(float x) {
    return 0.5f * x * (1.f + erff(x * 0.70710678118654752f));
}
__device__ __forceinline__ void split_bf16(float v, __nv_bfloat16& h, __nv_bfloat16& l) {
    h = __float2bfloat16(v);
    l = __float2bfloat16(v - __bfloat162float(h));
}

// ============ shared MMA machinery ===========================================
// CTA tile: 128 x (WNT*16), BK=32, 8 warps (4x2), warp tile 32 x (WNT*8).
// Stage layout: AHI@0 (8KB), ALO@8KB, BHI@16KB, BLO@16KB+BTILE.  BTILE=WNT*1024.
#define MBK 32
#define NSTAGE 3

template<int WNT>
__device__ __forceinline__ void mma_frag_offsets(int lane, int wm, int wn,
                                                 uint32_t (&aoff)[2][2],
                                                 uint32_t (&boff)[WNT / 2][2]) {
    int lr = lane & 15, lh = lane >> 4;
#pragma unroll
    for (int mt = 0; mt < 2; mt++)
#pragma unroll
        for (int ks = 0; ks < 2; ks++) {
            int row = wm * 32 + mt * 16 + lr;
            aoff[mt][ks] = swz((uint32_t)(row * 64 + (ks * 2 + lh) * 16));
        }
    int q = lane >> 3, rl = lane & 7;
#pragma unroll
    for (int p = 0; p < WNT / 2; p++)
#pragma unroll
        for (int ks = 0; ks < 2; ks++) {
            int n = wn * (WNT * 8) + p * 16 + ((q >> 1) << 3) + rl;
            boff[p][ks] = swz((uint32_t)(n * 64 + ((q & 1) + ks * 2) * 16));
        }
}

template<int WNT>
__device__ __forceinline__ void mma_compute_stage(uint32_t base,
                                                  const uint32_t (&aoff)[2][2],
                                                  const uint32_t (&boff)[WNT / 2][2],
                                                  float (&acc)[2][WNT][4]) {
    constexpr uint32_t BT = WNT * 1024;
#pragma unroll
    for (int ks = 0; ks < 2; ks++) {
        uint32_t ah[2][4], al[2][4], bh[WNT / 2][4], bl[WNT / 2][4];
#pragma unroll
        for (int mt = 0; mt < 2; mt++) {
            ldsm4(ah[mt], base +        aoff[mt][ks]);
            ldsm4(al[mt], base + 8192 + aoff[mt][ks]);
        }
#pragma unroll
        for (int p = 0; p < WNT / 2; p++) {
            ldsm4(bh[p], base + 16384 +      boff[p][ks]);
            ldsm4(bl[p], base + 16384 + BT + boff[p][ks]);
        }
#pragma unroll
        for (int mt = 0; mt < 2; mt++)
#pragma unroll
            for (int nt = 0; nt < WNT; nt++) {
                const uint32_t* bph = &bh[nt >> 1][(nt & 1) * 2];
                const uint32_t* bpl = &bl[nt >> 1][(nt & 1) * 2];
                mma16816(acc[mt][nt], ah[mt], bph);   // hi*hi
                mma16816(acc[mt][nt], ah[mt], bpl);   // hi*lo
                mma16816(acc[mt][nt], al[mt], bph);   // lo*hi
            }
    }
}

// ============ generic split-bf16 MMA GEMM ====================================
// EPI: 0 = Cout = acc + bias
//      2 = split(relu(acc + bias)) -> hi/lo
//      4 = split(acc)              -> hi/lo (no bias)
// BMB: B operand batch index derived from m0 (>>11) with stride sBb.
template<int EPI, int WNT, bool BMB>
__global__ void __launch_bounds__(256)
mma_gemm_kernel(const __nv_bfloat16* __restrict__ Ahi, const __nv_bfloat16* __restrict__ Alo,
                const __nv_bfloat16* __restrict__ Bhi, const __nv_bfloat16* __restrict__ Blo,
                float* __restrict__ Cout, const float* __restrict__ bias,
                __nv_bfloat16* __restrict__ hi_out, __nv_bfloat16* __restrict__ lo_out,
                int N, int K, size_t sBb)
{
    constexpr int MBN_ = WNT * 16;
    constexpr uint32_t BT = WNT * 1024;
    constexpr uint32_t STAGE = 16384 + 2 * BT;
    extern __shared__ char smem[];
    const uint32_t sb = smem_u32(smem);
    const int tid  = threadIdx.x;
    const int wid  = tid >> 5, lane = tid & 31;
    const int wm   = wid >> 1, wn = wid & 1;
    const int m0   = blockIdx.y * 128, n0 = blockIdx.x * MBN_;
    const size_t zB = (BMB ? (size_t)(m0 >> 11) : 0) * sBb;
    Bhi += zB; Blo += zB;

    uint32_t aoff[2][2], boff[WNT / 2][2];
    mma_frag_offsets<WNT>(lane, wm, wn, aoff, boff);

    float acc[2][WNT][4];
#pragma unroll
    for (int mt = 0; mt < 2; mt++)
#pragma unroll
        for (int nt = 0; nt < WNT; nt++)
#pragma unroll
            for (int j = 0; j < 4; j++) acc[mt][nt][j] = 0.f;

    auto load_stage = [&](int kt, int stg) {
        const uint32_t base = sb + stg * STAGE;
        const size_t kofs = (size_t)kt * MBK;
#pragma unroll
        for (int i = tid; i < 512; i += 256) {
            int r = i >> 2, c = i & 3;
            uint32_t so = swz((uint32_t)(r * 64 + c * 16));
            size_t g = (size_t)(m0 + r) * K + kofs + c * 8;
            cp_async16(base +        so, Ahi + g);
            cp_async16(base + 8192 + so, Alo + g);
        }
#pragma unroll
        for (int i = tid; i < MBN_ * 4; i += 256) {
            int r = i >> 2, c = i & 3;
            uint32_t so = swz((uint32_t)(r * 64 + c * 16));
            size_t g = (size_t)(n0 + r) * K + kofs + c * 8;
            cp_async16(base + 16384 +      so, Bhi + g);
            cp_async16(base + 16384 + BT + so, Blo + g);
        }
    };

    const int T = K / MBK;
    load_stage(0, 0); CP_COMMIT();
    load_stage(1, 1); CP_COMMIT();

    for (int kt = 0; kt < T; kt++) {
        if (kt + 1 < T) CP_WAIT(1); else CP_WAIT(0);
        __syncthreads();
        if (kt + 2 < T) { load_stage(kt + 2, (kt + 2) % NSTAGE); CP_COMMIT(); }
        mma_compute_stage<WNT>(sb + (kt % NSTAGE) * STAGE, aoff, boff, acc);
    }

    // ---- epilogue ------------------------------------------------------------
    const int lr = lane >> 2, lc = (lane & 3) * 2;
#pragma unroll
    for (int mt = 0; mt < 2; mt++)
#pragma unroll
        for (int nt = 0; nt < WNT; nt++) {
            int row = m0 + wm * 32 + mt * 16 + lr;
            int col = n0 + wn * (WNT * 8) + nt * 8 + lc;
            float b0 = 0.f, b1 = 0.f;
            if (EPI != 4) { b0 = __ldg(bias + col); b1 = __ldg(bias + col + 1); }
#pragma unroll
            for (int h = 0; h < 2; h++) {
                size_t o = (size_t)(row + h * 8) * N + col;
                float v0 = acc[mt][nt][h * 2 + 0] + b0;
                float v1 = acc[mt][nt][h * 2 + 1] + b1;
                if (EPI == 0) {
                    *(float2*)(Cout + o) = make_float2(v0, v1);
                } else {
                    if (EPI == 2) { v0 = fmaxf(v0, 0.f); v1 = fmaxf(v1, 0.f); }
                    __nv_bfloat16 h0, l0, h1, l1;
                    split_bf16(v0, h0, l0); split_bf16(v1, h1, l1);
                    *(__nv_bfloat162*)(hi_out + o) = __nv_bfloat162(h0, h1);
                    *(__nv_bfloat162*)(lo_out + o) = __nv_bfloat162(l0, l1);
                }
            }
        }
}

// ============ fused gemm6+gemm7 kernel =======================================
// Phase 1 (kt 0..1):  acc += P[m,:64] @ BmT[b][n,:64]      (coarse, K=64)
//   then acc = 10*gelu(acc)
// Phase 2 (kt 2..9):  acc += U[m,:256] @ w2T[n,:256]        (fine, K=256)
// Epilogue: split(0.1*(acc + b2)) -> Hhi/Hlo
__global__ void __launch_bounds__(256)
fused67_kernel(const float* __restrict__ b2) {
    constexpr int WNT = 8;
    constexpr uint32_t BT = WNT * 1024;
    constexpr uint32_t STAGE = 16384 + 2 * BT;     // 32KB
    constexpr int T1 = RANK / MBK;                 // 2
    constexpr int T  = T1 + TRH / MBK;             // 10
    extern __shared__ char smem[];
    const uint32_t sb = smem_u32(smem);
    const int tid  = threadIdx.x;
    const int wid  = tid >> 5, lane = tid & 31;
    const int wm   = wid >> 1, wn = wid & 1;
    const int m0   = blockIdx.y * 128, n0 = blockIdx.x * 128;
    const int b    = m0 >> 11;

    uint32_t aoff[2][2], boff[4][2];
    mma_frag_offsets<8>(lane, wm, wn, aoff, boff);

    float acc[2][8][4];
#pragma unroll
    for (int mt = 0; mt < 2; mt++)
#pragma unroll
        for (int nt = 0; nt < 8; nt++)
#pragma unroll
            for (int j = 0; j < 4; j++) acc[mt][nt][j] = 0.f;

    auto load_stage = [&](int kt, int stg) {
        const uint32_t base = sb + stg * STAGE;
        const __nv_bfloat16 *pAh, *pAl, *pBh, *pBl;
        int strd;
        if (kt < T1) {
            strd = RANK;
            size_t ao = (size_t)m0 * RANK + kt * MBK;
            size_t bo = ((size_t)b * DFF + n0) * RANK + kt * MBK;
            pAh = g_Phi + ao;   pAl = g_Plo + ao;
            pBh = g_BmThi + bo; pBl = g_BmTlo + bo;
        } else {
            strd = TRH;
            size_t ao = (size_t)m0 * TRH + (kt - T1) * MBK;
            size_t bo = (size_t)n0 * TRH + (kt - T1) * MBK;
            pAh = g_Uhi + ao;   pAl = g_Ulo + ao;
            pBh = g_w2Thi + bo; pBl = g_w2Tlo + bo;
        }
#pragma unroll
        for (int i = tid; i < 512; i += 256) {
            int r = i >> 2, c = i & 3;
            uint32_t so = swz((uint32_t)(r * 64 + c * 16));
            size_t g = (size_t)r * strd + c * 8;
            cp_async16(base +        so, pAh + g);
            cp_async16(base + 8192 + so, pAl + g);
        }
#pragma unroll
        for (int i = tid; i < 512; i += 256) {
            int r = i >> 2, c = i & 3;
            uint32_t so = swz((uint32_t)(r * 64 + c * 16));
            size_t g = (size_t)r * strd + c * 8;
            cp_async16(base + 16384 +      so, pBh + g);
            cp_async16(base + 16384 + BT + so, pBl + g);
        }
    };

    load_stage(0, 0); CP_COMMIT();
    load_stage(1, 1); CP_COMMIT();

    for (int kt = 0; kt < T; kt++) {
        if (kt + 1 < T) CP_WAIT(1); else CP_WAIT(0);
        __syncthreads();
        if (kt + 2 < T) { load_stage(kt + 2, (kt + 2) % NSTAGE); CP_COMMIT(); }
        mma_compute_stage<8>(sb + (kt % NSTAGE) * STAGE, aoff, boff, acc);
        if (kt == T1 - 1) {
#pragma unroll
            for (int mt = 0; mt < 2; mt++)
#pragma unroll
                for (int nt = 0; nt < 8; nt++)
#pragma unroll
                    for (int j = 0; j < 4; j++)
                        acc[mt][nt][j] = 10.f * gelu_f(acc[mt][nt][j]);
        }
    }

    // ---- epilogue: split(0.1*(acc + b2)) ------------------------------------
    const int lr = lane >> 2, lc = (lane & 3) * 2;
#pragma unroll
    for (int mt = 0; mt < 2; mt++)
#pragma unroll
        for (int nt = 0; nt < 8; nt++) {
            int row = m0 + wm * 32 + mt * 16 + lr;
            int col = n0 + wn * 64 + nt * 8 + lc;
            float b0 = __ldg(b2 + col), b1 = __ldg(b2 + col + 1);
#pragma unroll
            for (int h = 0; h < 2; h++) {
                size_t o = (size_t)(row + h * 8) * DFF + col;
                float v0 = RES_SCALE * (acc[mt][nt][h * 2 + 0] + b0);
                float v1 = RES_SCALE * (acc[mt][nt][h * 2 + 1] + b1);
                __nv_bfloat16 h0, l0, h1, l1;
                split_bf16(v0, h0, l0); split_bf16(v1, h1, l1);
                *(__nv_bfloat162*)(g_Hhi + o) = __nv_bfloat162(h0, h1);
                *(__nv_bfloat162*)(g_Hlo + o) = __nv_bfloat162(l0, l1);
            }
        }
}

// ---------------- sentence coefficients -------------------------------------
__global__ void coef_kernel(const int* __restrict__ nidx, const float* __restrict__ w,
                            const float* __restrict__ cA, const float* __restrict__ cB,
                            float* __restrict__ outA, float* __restrict__ outB) {
    const int b   = blockIdx.x;
    const int tid = threadIdx.x;
    const int NK  = S_ * KSEL;
    float accA[NB] = {}, accB[NB] = {};
    float ws = 0.f;
    for (int n = tid; n < NK; n += 256) {
        float wv = w[b * NK + n];
        int   id = nidx[b * NK + n];
        ws += wv;
        const float4* pa = (const float4*)(cA + (size_t)id * NB);
        const float4* pb = (const float4*)(cB + (size_t)id * NB);
#pragma unroll
        for (int q = 0; q < 4; q++) {
            float4 va = pa[q], vb = pb[q];
            accA[q*4+0] += wv * va.x; accA[q*4+1] += wv * va.y;
            accA[q*4+2] += wv * va.z; accA[q*4+3] += wv * va.w;
            accB[q*4+0] += wv * vb.x; accB[q*4+1] += wv * vb.y;
            accB[q*4+2] += wv * vb.z; accB[q*4+3] += wv * vb.w;
        }
    }
    __shared__ float sbuf[33][9];
    __shared__ float sfin[33];
    const int lane = tid & 31, wid = tid >> 5;
    auto wred = [](float v) {
#pragma unroll
        for (int o = 16; o > 0; o >>= 1) v += __shfl_down_sync(0xffffffffu, v, o);
        return v;
    };
    float r = wred(ws);
    if (lane == 0) sbuf[0][wid] = r;
#pragma unroll
    for (int i = 0; i < NB; i++) { float v = wred(accA[i]); if (lane == 0) sbuf[1 + i][wid] = v; }
#pragma unroll
    for (int i = 0; i < NB; i++) { float v = wred(accB[i]); if (lane == 0) sbuf[17 + i][wid] = v; }
    __syncthreads();
    if (tid < 33) {
        float s = 0.f;
#pragma unroll
        for (int j = 0; j < 8; j++) s += sbuf[tid][j];
        sfin[tid] = s;
    }
    __syncthreads();
    const float denom = sfin[0] + EPSN;
    if (tid < NB)            outA[b * NB + tid]        = sfin[1 + tid]  / denom;
    else if (tid < 2 * NB)   outB[b * NB + (tid - NB)] = sfin[17 + tid - NB] / denom;
}

// ================= merged prep kernel (grid-range dispatch) ==================
#define PR_TS0   0            // 16384 blocks : token_sig -> ts hi/lo
#define PR_XS0   16384        // 16384 blocks : x -> x hi/lo (elementwise)
#define PR_AT0   32768        // 128 blocks   : build AT hi/lo [b][r][d]
#define PR_BBT0  32896        // 512 blocks   : build BmT hi/lo [b][f][r]
#define PR_TDW0  33408        // 4096 blocks  : transpose+split down_w
#define PR_TW20  37504        // 1024 blocks  : transpose+split w2
#define PR_TW10  38528        // 256 blocks   : transpose+split w1
#define PR_END   38784

__device__ __forceinline__ void prep_transpose(const float* __restrict__ in,
                                               __nv_bfloat16* __restrict__ ohi,
                                               __nv_bfloat16* __restrict__ olo,
                                               int R, int C, int gx, int gy,
                                               float* tile /*[32][33]*/) {
    const int tid = threadIdx.x;
    const int tx = tid & 31, ty = tid >> 5;
    const int c0 = gx * 32, r0 = gy * 32;
#pragma unroll
    for (int j = 0; j < 32; j += 8)
        tile[(ty + j) * 33 + tx] = in[(size_t)(r0 + ty + j) * C + c0 + tx];
    __syncthreads();
#pragma unroll
    for (int j = 0; j < 32; j += 8) {
        float v = tile[tx * 33 + ty + j];
        size_t o = (size_t)(c0 + ty + j) * R + r0 + tx;
        __nv_bfloat16 h, l; split_bf16(v, h, l);
        ohi[o] = h; olo[o] = l;
    }
}

__global__ void __launch_bounds__(256)
prep_kernel(const float* __restrict__ x,
            const float* __restrict__ sel, const float* __restrict__ w,
            const float* __restrict__ basisA, const float* __restrict__ basisB,
            const float* __restrict__ w1, const float* __restrict__ w2,
            const float* __restrict__ dw) {
    __shared__ float tile[64 * 65];
    const int blk = blockIdx.x;
    const int tid = threadIdx.x;

    if (blk < PR_XS0) {
        // ---- token_sig ----
        int t = blk * 256 + tid;
        int d4 = t & 255;
        int bs = t >> 8;
        const float* base = sel + (size_t)bs * KSEL * DM + d4 * 4;
        const float* wp   = w + (size_t)bs * KSEL;
        float4 acc = make_float4(0, 0, 0, 0);
#pragma unroll
        for (int k = 0; k < KSEL; k++) {
            float  wv = wp[k];
            float4 v  = *(const float4*)(base + k * DM);
            acc.x += wv * v.x; acc.y += wv * v.y; acc.z += wv * v.z; acc.w += wv * v.w;
        }
        union { __nv_bfloat16 b[4]; uint2 u; } ph, pl;
        split_bf16(acc.x, ph.b[0], pl.b[0]);
        split_bf16(acc.y, ph.b[1], pl.b[1]);
        split_bf16(acc.z, ph.b[2], pl.b[2]);
        split_bf16(acc.w, ph.b[3], pl.b[3]);
        size_t o = (size_t)bs * DM + d4 * 4;
        *(uint2*)(g_tshi + o) = ph.u;
        *(uint2*)(g_tslo + o) = pl.u;
    } else if (blk < PR_AT0) {
        // ---- x split (elementwise) ----
        size_t t = (size_t)(blk - PR_XS0) * 256 + tid;
        size_t e = t * 4;
        float4 v = *(const float4*)(x + e);
        union { __nv_bfloat16 b[4]; uint2 u; } ph, pl;
        split_bf16(v.x, ph.b[0], pl.b[0]);
        split_bf16(v.y, ph.b[1], pl.b[1]);
        split_bf16(v.z, ph.b[2], pl.b[2]);
        split_bf16(v.w, ph.b[3], pl.b[3]);
        *(uint2*)(g_xhi + e) = ph.u;
        *(uint2*)(g_xlo + e) = pl.u;
    } else if (blk < PR_BBT0) {
        // ---- build AT hi/lo: AT[b][r][d] = sum_i cA[b,i]*basisA[i][d][r] ----
        int lb = blk - PR_AT0;             // 0..127
        int b  = lb >> 4;
        int d0 = (lb & 15) * 64;
        int dl = tid >> 2;                 // 0..63
        int rq = tid & 3;
        float accv[16];
#pragma unroll
        for (int j = 0; j < 16; j++) accv[j] = 0.f;
#pragma unroll
        for (int i = 0; i < NB; i++) {
            float c = g_coefA[b * NB + i];
            const float* src = basisA + ((size_t)i * DM + d0 + dl) * RANK + rq * 16;
#pragma unroll
            for (int q = 0; q < 4; q++) {
                float4 v = *(const float4*)(src + q * 4);
                accv[q*4+0] += c * v.x; accv[q*4+1] += c * v.y;
                accv[q*4+2] += c * v.z; accv[q*4+3] += c * v.w;
            }
        }
#pragma unroll
        for (int j = 0; j < 16; j++) tile[dl * 65 + rq * 16 + j] = accv[j];
        __syncthreads();
        int r  = tid >> 2;                 // 0..63
        int dq = tid & 3;
        size_t obase = ((size_t)b * RANK + r) * DM + d0 + dq * 16;
        __nv_bfloat16 hv[16], lv[16];
#pragma unroll
        for (int j = 0; j < 16; j++) {
            float v = tile[(dq * 16 + j) * 65 + r];
            split_bf16(v, hv[j], lv[j]);
        }
#pragma unroll
        for (int j = 0; j < 16; j += 8) {
            *(uint4*)(g_AThi + obase + j) = *(uint4*)(hv + j);
            *(uint4*)(g_ATlo + obase + j) = *(uint4*)(lv + j);
        }
    } else if (blk < PR_TDW0) {
        // ---- build BmT hi/lo: out[b][f][r] = sum_i cB[b,i]*basis_B[i][r][f] ----
        int lb = blk - PR_BBT0;            // 0..511
        int f0 = (lb & 63) * 64;
        int b  = lb >> 6;
        int r  = tid >> 2;                 // 0..63
        int fq = tid & 3;
        float accv[16];
#pragma unroll
        for (int j = 0; j < 16; j++) accv[j] = 0.f;
#pragma unroll
        for (int i = 0; i < NB; i++) {
            float c = g_coefB[b * NB + i];
            const float* src = basisB + ((size_t)i * RANK + r) * DFF + f0 + fq * 16;
#pragma unroll
            for (int q = 0; q < 4; q++) {
                float4 v = *(const float4*)(src + q * 4);
                accv[q*4+0] += c * v.x; accv[q*4+1] += c * v.y;
                accv[q*4+2] += c * v.z; accv[q*4+3] += c * v.w;
            }
        }
#pragma unroll
        for (int j = 0; j < 16; j++) tile[r * 65 + fq * 16 + j] = accv[j];
        __syncthreads();
        int f  = tid >> 2;
        int rq2 = tid & 3;
        size_t obase = ((size_t)b * DFF + f0 + f) * RANK + rq2 * 16;
        __nv_bfloat16 hv[16], lv[16];
#pragma unroll
        for (int j = 0; j < 16; j++) {
            float v = tile[(rq2 * 16 + j) * 65 + f];
            split_bf16(v, hv[j], lv[j]);
        }
#pragma unroll
        for (int j = 0; j < 16; j += 8) {
            *(uint4*)(g_BmThi + obase + j) = *(uint4*)(hv + j);
            *(uint4*)(g_BmTlo + obase + j) = *(uint4*)(lv + j);
        }
    } else if (blk < PR_TW20) {
        int lb = blk - PR_TDW0;            // dw: R=DFF, C=DM, grid (32 x 128)
        prep_transpose(dw, g_dwThi, g_dwTlo, DFF, DM, lb & 31, lb >> 5, tile);
    } else if (blk < PR_TW10) {
        int lb = blk - PR_TW20;            // w2: R=TRH, C=DFF, grid (128 x 8)
        prep_transpose(w2, g_w2Thi, g_w2Tlo, TRH, DFF, lb & 127, lb >> 7, tile);
    } else {
        int lb = blk - PR_TW10;            // w1: R=DM, C=TRH, grid (8 x 32)
        prep_transpose(w1, g_w1Thi, g_w1Tlo, DM, TRH, lb & 7, lb >> 3, tile);
    }
}

// ---------------- launch -----------------------------------------------------
extern "C" void kernel_launch(void* const* d_in, const int* in_sizes, int n_in,
                              void* d_out, int out_size) {
    (void)in_sizes; (void)n_in; (void)out_size;
    const float* x    = (const float*)d_in[0];
    const float* sel  = (const float*)d_in[1];
    const int*   nidx = (const int*)  d_in[2];
    const float* nw   = (const float*)d_in[3];
    const float* bA   = (const float*)d_in[4];
    const float* bB   = (const float*)d_in[5];
    const float* cA   = (const float*)d_in[6];
    const float* cB   = (const float*)d_in[7];
    const float* w1   = (const float*)d_in[8];
    const float* b1   = (const float*)d_in[9];
    const float* w2   = (const float*)d_in[10];
    const float* b2   = (const float*)d_in[11];
    const float* dw   = (const float*)d_in[12];
    const float* db   = (const float*)d_in[13];
    float* out = (float*)d_out;

    float *pCA, *pCB;
    __nv_bfloat16 *pXh, *pXl, *pATh, *pATl, *pPh, *pPl;
    __nv_bfloat16 *pTsh, *pTsl, *pUh, *pUl, *pHh, *pHl;
    __nv_bfloat16 *pW1h, *pW1l, *pDWh, *pDWl;
    cudaGetSymbolAddress((void**)&pCA,  g_coefA);
    cudaGetSymbolAddress((void**)&pCB,  g_coefB);
    cudaGetSymbolAddress((void**)&pXh,  g_xhi);
    cudaGetSymbolAddress((void**)&pXl,  g_xlo);
    cudaGetSymbolAddress((void**)&pATh, g_AThi);
    cudaGetSymbolAddress((void**)&pATl, g_ATlo);
    cudaGetSymbolAddress((void**)&pPh,  g_Phi);
    cudaGetSymbolAddress((void**)&pPl,  g_Plo);
    cudaGetSymbolAddress((void**)&pTsh, g_tshi);
    cudaGetSymbolAddress((void**)&pTsl, g_tslo);
    cudaGetSymbolAddress((void**)&pUh,  g_Uhi);
    cudaGetSymbolAddress((void**)&pUl,  g_Ulo);
    cudaGetSymbolAddress((void**)&pHh,  g_Hhi);
    cudaGetSymbolAddress((void**)&pHl,  g_Hlo);
    cudaGetSymbolAddress((void**)&pW1h, g_w1Thi);
    cudaGetSymbolAddress((void**)&pW1l, g_w1Tlo);
    cudaGetSymbolAddress((void**)&pDWh, g_dwThi);
    cudaGetSymbolAddress((void**)&pDWl, g_dwTlo);

    constexpr int SM8 = NSTAGE * (16384 + 2 * 8 * 1024);   // 98304
    constexpr int SM4 = NSTAGE * (16384 + 2 * 4 * 1024);   // 73728
    cudaFuncSetAttribute(mma_gemm_kernel<2, 8, false>, cudaFuncAttributeMaxDynamicSharedMemorySize, SM8);
    cudaFuncSetAttribute(mma_gemm_kernel<4, 4, true>,  cudaFuncAttributeMaxDynamicSharedMemorySize, SM4);
    cudaFuncSetAttribute(mma_gemm_kernel<0, 8, false>, cudaFuncAttributeMaxDynamicSharedMemorySize, SM8);
    cudaFuncSetAttribute(fused67_kernel, cudaFuncAttributeMaxDynamicSharedMemorySize, SM8);

    // 1. sentence coefficients
    coef_kernel<<<B_, 256>>>(nidx, nw, cA, cB, pCA, pCB);
    // 2. prep: token_sig + x-split + AT + BmT + weight transposes
    prep_kernel<<<PR_END, 256>>>(x, sel, nw, bA, bB, w1, w2, dw);
    // 3. U = relu(ts @ w1 + b1) -> hi/lo    (M=16384 N=256 K=1024)
    {
        dim3 grid(TRH / 128, BS_ / 128);
        mma_gemm_kernel<2, 8, false><<<grid, 256, SM8>>>(
            pTsh, pTsl, pW1h, pW1l, nullptr, b1, pUh, pUl, TRH, DM, 0);
    }
    // 4. P = x @ A[b] -> hi/lo   (M=16384 N=64 K=1024, B batched by m)
    {
        dim3 grid(1, BS_ / 128);
        mma_gemm_kernel<4, 4, true><<<grid, 256, SM4>>>(
            pXh, pXl, pATh, pATl, nullptr, nullptr, pPh, pPl,
            RANK, DM, (size_t)RANK * DM);
    }
    // 5. fused: Hsplit = gelu(P@BmT[b]) + 0.1*(U@w2 + b2)   (M=16384 N=4096)
    {
        dim3 grid(DFF / 128, BS_ / 128);
        fused67_kernel<<<grid, 256, SM8>>>(b2);
    }
    // 6. out = Hsplit @ down_w + db   (M=16384 N=1024 K=4096) — PROFILED
    {
        dim3 grid(DM / 128, BS_ / 128);
        mma_gemm_kernel<0, 8, false><<<grid, 256, SM8>>>(
            pHh, pHl, pDWh, pDWl, out, db, nullptr, nullptr, DM, DFF, 0);
    }
}

// round 8
// speedup vs baseline: 3.6500x; 1.0317x over previous
#include <cuda_runtime.h>
#include <cuda_bf16.h>
#include <math.h>
#include <stdint.h>

#define B_   8
#define S_   2048
#define KSEL 8
#define DM   1024
#define DFF  4096
#define NB   16
#define RANK 64
#define TRH  256
#define BS_  (B_ * S_)          // 16384 tokens
#define EPSN 1e-8f
#define RES_SCALE 0.1f

// ---------------- scratch (static device globals; no allocations) -------------
__device__ float g_coefA[B_ * NB];
__device__ float g_coefB[B_ * NB];
__device__ __nv_bfloat16 g_xhi [(size_t)BS_ * DM];
__device__ __nv_bfloat16 g_xlo [(size_t)BS_ * DM];
__device__ __nv_bfloat16 g_AThi[(size_t)B_ * RANK * DM];        // [b][r][d]
__device__ __nv_bfloat16 g_ATlo[(size_t)B_ * RANK * DM];
__device__ __nv_bfloat16 g_Phi [(size_t)BS_ * RANK];
__device__ __nv_bfloat16 g_Plo [(size_t)BS_ * RANK];
__device__ __nv_bfloat16 g_BmThi[(size_t)B_ * DFF * RANK];      // [b][f][r]
__device__ __nv_bfloat16 g_BmTlo[(size_t)B_ * DFF * RANK];
__device__ __nv_bfloat16 g_tshi[(size_t)BS_ * DM];
__device__ __nv_bfloat16 g_tslo[(size_t)BS_ * DM];
__device__ __nv_bfloat16 g_Uhi [(size_t)BS_ * TRH];
__device__ __nv_bfloat16 g_Ulo [(size_t)BS_ * TRH];
__device__ __nv_bfloat16 g_Hhi [(size_t)BS_ * DFF];
__device__ __nv_bfloat16 g_Hlo [(size_t)BS_ * DFF];
__device__ __nv_bfloat16 g_w1Thi[(size_t)TRH * DM];             // w1^T [256][1024]
__device__ __nv_bfloat16 g_w1Tlo[(size_t)TRH * DM];
__device__ __nv_bfloat16 g_w2Thi[(size_t)DFF * TRH];            // w2^T [4096][256]
__device__ __nv_bfloat16 g_w2Tlo[(size_t)DFF * TRH];
__device__ __nv_bfloat16 g_dwThi[(size_t)DM * DFF];             // down_w^T [1024][4096]
__device__ __nv_bfloat16 g_dwTlo[(size_t)DM * DFF];

// ======================= PTX helpers =========================================
__device__ __forceinline__ uint32_t smem_u32(const void* p) {
    uint32_t a;
    asm("{ .reg .u64 t; cvta.to.shared.u64 t, %1; cvt.u32.u64 %0, t; }" : "=r"(a) : "l"(p));
    return a;
}
__device__ __forceinline__ void cp_async16(uint32_t saddr, const void* g) {
    asm volatile("cp.async.cg.shared.global [%0], [%1], 16;" :: "r"(saddr), "l"(g));
}
#define CP_COMMIT() asm volatile("cp.async.commit_group;" ::: "memory")
#define CP_WAIT(n)  asm volatile("cp.async.wait_group %0;" :: "n"(n) : "memory")

__device__ __forceinline__ void ldsm4(uint32_t* r, uint32_t addr) {
    asm volatile("ldmatrix.sync.aligned.m8n8.x4.shared.b16 {%0,%1,%2,%3}, [%4];"
                 : "=r"(r[0]), "=r"(r[1]), "=r"(r[2]), "=r"(r[3]) : "r"(addr));
}
__device__ __forceinline__ void mma16816(float* d, const uint32_t* a, const uint32_t* b) {
    asm volatile("mma.sync.aligned.m16n8k16.row.col.f32.bf16.bf16.f32 "
                 "{%0,%1,%2,%3}, {%4,%5,%6,%7}, {%8,%9}, {%0,%1,%2,%3};"
                 : "+f"(d[0]), "+f"(d[1]), "+f"(d[2]), "+f"(d[3])
                 : "r"(a[0]), "r"(a[1]), "r"(a[2]), "r"(a[3]), "r"(b[0]), "r"(b[1]));
}
// XOR swizzle inside a tile of 64B rows: bits[4:5] ^= row bits[1:2]
__device__ __forceinline__ uint32_t swz(uint32_t byte) {
    return byte ^ (((byte >> 7) & 3u) << 4);
}
__device__ __forceinline__ float gelu_f(float x) {
    return 0.5f * x * (1.f + erff(x * 0.70710678118654752f));
}
__device__ __forceinline__ void split_bf16(float v, __nv_bfloat16& h, __nv_bfloat16& l) {
    h = __float2bfloat16(v);
    l = __float2bfloat16(v - __bfloat162float(h));
}

// ============ shared MMA machinery ===========================================
#define MBK 32

template<int WNT>
__device__ __forceinline__ void mma_frag_offsets(int lane, int wm, int wn,
                                                 uint32_t (&aoff)[2][2],
                                                 uint32_t (&boff)[WNT / 2][2]) {
    int lr = lane & 15, lh = lane >> 4;
#pragma unroll
    for (int mt = 0; mt < 2; mt++)
#pragma unroll
        for (int ks = 0; ks < 2; ks++) {
            int row = wm * 32 + mt * 16 + lr;
            aoff[mt][ks] = swz((uint32_t)(row * 64 + (ks * 2 + lh) * 16));
        }
    int q = lane >> 3, rl = lane & 7;
#pragma unroll
    for (int p = 0; p < WNT / 2; p++)
#pragma unroll
        for (int ks = 0; ks < 2; ks++) {
            int n = wn * (WNT * 8) + p * 16 + ((q >> 1) << 3) + rl;
            boff[p][ks] = swz((uint32_t)(n * 64 + ((q & 1) + ks * 2) * 16));
        }
}

// B processed in pairs of p (4 nt at a time) to bound live registers.
template<int WNT, uint32_t BT>
__device__ __forceinline__ void mma_compute_stage(uint32_t base,
                                                  const uint32_t (&aoff)[2][2],
                                                  const uint32_t (&boff)[WNT / 2][2],
                                                  float (&acc)[2][WNT][4]) {
#pragma unroll
    for (int ks = 0; ks < 2; ks++) {
        uint32_t ah[2][4], al[2][4];
#pragma unroll
        for (int mt = 0; mt < 2; mt++) {
            ldsm4(ah[mt], base +        aoff[mt][ks]);
            ldsm4(al[mt], base + 8192 + aoff[mt][ks]);
        }
#pragma unroll
        for (int ph = 0; ph < WNT / 4; ph++) {
            uint32_t bh[2][4], bl[2][4];
#pragma unroll
            for (int pp = 0; pp < 2; pp++) {
                int p = ph * 2 + pp;
                ldsm4(bh[pp], base + 16384 +      boff[p][ks]);
                ldsm4(bl[pp], base + 16384 + BT + boff[p][ks]);
            }
#pragma unroll
            for (int mt = 0; mt < 2; mt++)
#pragma unroll
                for (int nt2 = 0; nt2 < 4; nt2++) {
                    int nt = ph * 4 + nt2;
                    const uint32_t* bph = &bh[nt2 >> 1][(nt2 & 1) * 2];
                    const uint32_t* bpl = &bl[nt2 >> 1][(nt2 & 1) * 2];
                    mma16816(acc[mt][nt], ah[mt], bph);   // hi*hi
                    mma16816(acc[mt][nt], ah[mt], bpl);   // hi*lo
                    mma16816(acc[mt][nt], al[mt], bph);   // lo*hi
                }
        }
    }
}

// ============ gemm8: out = Hsplit @ dwT^T + db  (WNT=8, 2 CTA/SM) =============
#define ST8 32768u
#define SM8 (2 * ST8)
__global__ void __launch_bounds__(256, 2)
gemm8_kernel(float* __restrict__ Cout, const float* __restrict__ bias) {
    extern __shared__ char smem[];
    const uint32_t sb = smem_u32(smem);
    const int tid  = threadIdx.x;
    const int wid  = tid >> 5, lane = tid & 31;
    const int wm   = wid >> 1, wn = wid & 1;
    const int m0   = blockIdx.y * 128, n0 = blockIdx.x * 128;

    uint32_t aoff[2][2], boff[4][2];
    mma_frag_offsets<8>(lane, wm, wn, aoff, boff);

    float acc[2][8][4];
#pragma unroll
    for (int mt = 0; mt < 2; mt++)
#pragma unroll
        for (int nt = 0; nt < 8; nt++)
#pragma unroll
            for (int j = 0; j < 4; j++) acc[mt][nt][j] = 0.f;

    auto load_stage = [&](int kt, int stg) {
        const uint32_t base = sb + stg * ST8;
        const size_t kofs = (size_t)kt * MBK;
#pragma unroll
        for (int i = tid; i < 512; i += 256) {
            int r = i >> 2, c = i & 3;
            uint32_t so = swz((uint32_t)(r * 64 + c * 16));
            size_t gA = (size_t)(m0 + r) * DFF + kofs + c * 8;
            size_t gB = (size_t)(n0 + r) * DFF + kofs + c * 8;
            cp_async16(base +         so, g_Hhi + gA);
            cp_async16(base +  8192 + so, g_Hlo + gA);
            cp_async16(base + 16384 + so, g_dwThi + gB);
            cp_async16(base + 24576 + so, g_dwTlo + gB);
        }
    };

    constexpr int T = DFF / MBK;
    load_stage(0, 0); CP_COMMIT();
    for (int kt = 0; kt < T; kt++) {
        CP_WAIT(0);
        __syncthreads();
        if (kt + 1 < T) { load_stage(kt + 1, (kt + 1) & 1); CP_COMMIT(); }
        mma_compute_stage<8, 8192u>(sb + (kt & 1) * ST8, aoff, boff, acc);
    }

    const int lr = lane >> 2, lc = (lane & 3) * 2;
#pragma unroll
    for (int mt = 0; mt < 2; mt++)
#pragma unroll
        for (int nt = 0; nt < 8; nt++) {
            int row = m0 + wm * 32 + mt * 16 + lr;
            int col = n0 + wn * 64 + nt * 8 + lc;
            float b0 = __ldg(bias + col), b1 = __ldg(bias + col + 1);
#pragma unroll
            for (int h = 0; h < 2; h++) {
                size_t o = (size_t)(row + h * 8) * DM + col;
                *(float2*)(Cout + o) = make_float2(acc[mt][nt][h * 2 + 0] + b0,
                                                   acc[mt][nt][h * 2 + 1] + b1);
            }
        }
}

// ============ fused gemm6+gemm7 (WNT=8, 2 CTA/SM) ============================
__global__ void __launch_bounds__(256, 2)
fused67_kernel(const float* __restrict__ b2) {
    constexpr int T1 = RANK / MBK;                 // 2
    constexpr int T  = T1 + TRH / MBK;             // 10
    extern __shared__ char smem[];
    const uint32_t sb = smem_u32(smem);
    const int tid  = threadIdx.x;
    const int wid  = tid >> 5, lane = tid & 31;
    const int wm   = wid >> 1, wn = wid & 1;
    const int m0   = blockIdx.y * 128, n0 = blockIdx.x * 128;
    const int b    = m0 >> 11;

    uint32_t aoff[2][2], boff[4][2];
    mma_frag_offsets<8>(lane, wm, wn, aoff, boff);

    float acc[2][8][4];
#pragma unroll
    for (int mt = 0; mt < 2; mt++)
#pragma unroll
        for (int nt = 0; nt < 8; nt++)
#pragma unroll
            for (int j = 0; j < 4; j++) acc[mt][nt][j] = 0.f;

    auto load_stage = [&](int kt, int stg) {
        const uint32_t base = sb + stg * ST8;
        const __nv_bfloat16 *pAh, *pAl, *pBh, *pBl;
        int strd;
        if (kt < T1) {
            strd = RANK;
            size_t ao = (size_t)m0 * RANK + kt * MBK;
            size_t bo = ((size_t)b * DFF + n0) * RANK + kt * MBK;
            pAh = g_Phi + ao;   pAl = g_Plo + ao;
            pBh = g_BmThi + bo; pBl = g_BmTlo + bo;
        } else {
            strd = TRH;
            size_t ao = (size_t)m0 * TRH + (kt - T1) * MBK;
            size_t bo = (size_t)n0 * TRH + (kt - T1) * MBK;
            pAh = g_Uhi + ao;   pAl = g_Ulo + ao;
            pBh = g_w2Thi + bo; pBl = g_w2Tlo + bo;
        }
#pragma unroll
        for (int i = tid; i < 512; i += 256) {
            int r = i >> 2, c = i & 3;
            uint32_t so = swz((uint32_t)(r * 64 + c * 16));
            size_t g = (size_t)r * strd + c * 8;
            cp_async16(base +         so, pAh + g);
            cp_async16(base +  8192 + so, pAl + g);
            cp_async16(base + 16384 + so, pBh + g);
            cp_async16(base + 24576 + so, pBl + g);
        }
    };

    load_stage(0, 0); CP_COMMIT();
    for (int kt = 0; kt < T; kt++) {
        CP_WAIT(0);
        __syncthreads();
        if (kt + 1 < T) { load_stage(kt + 1, (kt + 1) & 1); CP_COMMIT(); }
        mma_compute_stage<8, 8192u>(sb + (kt & 1) * ST8, aoff, boff, acc);
        if (kt == T1 - 1) {
#pragma unroll
            for (int mt = 0; mt < 2; mt++)
#pragma unroll
                for (int nt = 0; nt < 8; nt++)
#pragma unroll
                    for (int j = 0; j < 4; j++)
                        acc[mt][nt][j] = 10.f * gelu_f(acc[mt][nt][j]);
        }
    }

    const int lr = lane >> 2, lc = (lane & 3) * 2;
#pragma unroll
    for (int mt = 0; mt < 2; mt++)
#pragma unroll
        for (int nt = 0; nt < 8; nt++) {
            int row = m0 + wm * 32 + mt * 16 + lr;
            int col = n0 + wn * 64 + nt * 8 + lc;
            float b0 = __ldg(b2 + col), b1 = __ldg(b2 + col + 1);
#pragma unroll
            for (int h = 0; h < 2; h++) {
                size_t o = (size_t)(row + h * 8) * DFF + col;
                float v0 = RES_SCALE * (acc[mt][nt][h * 2 + 0] + b0);
                float v1 = RES_SCALE * (acc[mt][nt][h * 2 + 1] + b1);
                __nv_bfloat16 h0, l0, h1, l1;
                split_bf16(v0, h0, l0); split_bf16(v1, h1, l1);
                *(__nv_bfloat162*)(g_Hhi + o) = __nv_bfloat162(h0, h1);
                *(__nv_bfloat162*)(g_Hlo + o) = __nv_bfloat162(l0, l1);
            }
        }
}

// ============ combined gemm4+gemm5 (WNT=4, 2 CTA/SM) =========================
// blockIdx.x 0..3 : gemm5  U = relu(ts @ w1T + b1) -> hi/lo   (N=256, 64/blk)
// blockIdx.x == 4 : gemm4  P = x @ AT[b] -> hi/lo             (N=64)
#define ST4 24576u
#define SM4 (2 * ST4)
__global__ void __launch_bounds__(256, 2)
gemm45_kernel(const float* __restrict__ bias1) {
    extern __shared__ char smem[];
    const uint32_t sb = smem_u32(smem);
    const int tid  = threadIdx.x;
    const int wid  = tid >> 5, lane = tid & 31;
    const int wm   = wid >> 1, wn = wid & 1;
    const int m0   = blockIdx.y * 128;
    const bool is4 = (blockIdx.x == 4);
    const int n0   = is4 ? 0 : blockIdx.x * 64;

    const __nv_bfloat16 *Ahi, *Alo, *Bhi, *Blo;
    if (is4) {
        Ahi = g_xhi; Alo = g_xlo;
        size_t bo = (size_t)(m0 >> 11) * RANK * DM;
        Bhi = g_AThi + bo; Blo = g_ATlo + bo;
    } else {
        Ahi = g_tshi; Alo = g_tslo;
        size_t bo = (size_t)n0 * DM;
        Bhi = g_w1Thi + bo; Blo = g_w1Tlo + bo;
    }

    uint32_t aoff[2][2], boff[2][2];
    mma_frag_offsets<4>(lane, wm, wn, aoff, boff);

    float acc[2][4][4];
#pragma unroll
    for (int mt = 0; mt < 2; mt++)
#pragma unroll
        for (int nt = 0; nt < 4; nt++)
#pragma unroll
            for (int j = 0; j < 4; j++) acc[mt][nt][j] = 0.f;

    auto load_stage = [&](int kt, int stg) {
        const uint32_t base = sb + stg * ST4;
        const size_t kofs = (size_t)kt * MBK;
#pragma unroll
        for (int i = tid; i < 512; i += 256) {
            int r = i >> 2, c = i & 3;
            uint32_t so = swz((uint32_t)(r * 64 + c * 16));
            size_t gA = (size_t)(m0 + r) * DM + kofs + c * 8;
            cp_async16(base +        so, Ahi + gA);
            cp_async16(base + 8192 + so, Alo + gA);
        }
        {
            int i = tid;
            if (i < 256) {
                int r = i >> 2, c = i & 3;
                uint32_t so = swz((uint32_t)(r * 64 + c * 16));
                size_t gB = (size_t)r * DM + kofs + c * 8;
                cp_async16(base + 16384 + so, Bhi + gB);
                cp_async16(base + 20480 + so, Blo + gB);
            }
        }
    };

    constexpr int T = DM / MBK;     // 32
    load_stage(0, 0); CP_COMMIT();
    for (int kt = 0; kt < T; kt++) {
        CP_WAIT(0);
        __syncthreads();
        if (kt + 1 < T) { load_stage(kt + 1, (kt + 1) & 1); CP_COMMIT(); }
        mma_compute_stage<4, 4096u>(sb + (kt & 1) * ST4, aoff, boff, acc);
    }

    const int lr = lane >> 2, lc = (lane & 3) * 2;
#pragma unroll
    for (int mt = 0; mt < 2; mt++)
#pragma unroll
        for (int nt = 0; nt < 4; nt++) {
            int row = m0 + wm * 32 + mt * 16 + lr;
            int col = n0 + wn * 32 + nt * 8 + lc;
#pragma unroll
            for (int h = 0; h < 2; h++) {
                float v0 = acc[mt][nt][h * 2 + 0];
                float v1 = acc[mt][nt][h * 2 + 1];
                __nv_bfloat16 h0, l0, h1, l1;
                if (is4) {
                    size_t o = (size_t)(row + h * 8) * RANK + col;
                    split_bf16(v0, h0, l0); split_bf16(v1, h1, l1);
                    *(__nv_bfloat162*)(g_Phi + o) = __nv_bfloat162(h0, h1);
                    *(__nv_bfloat162*)(g_Plo + o) = __nv_bfloat162(l0, l1);
                } else {
                    size_t o = (size_t)(row + h * 8) * TRH + col;
                    v0 = fmaxf(v0 + __ldg(bias1 + col), 0.f);
                    v1 = fmaxf(v1 + __ldg(bias1 + col + 1), 0.f);
                    split_bf16(v0, h0, l0); split_bf16(v1, h1, l1);
                    *(__nv_bfloat162*)(g_Uhi + o) = __nv_bfloat162(h0, h1);
                    *(__nv_bfloat162*)(g_Ulo + o) = __nv_bfloat162(l0, l1);
                }
            }
        }
}

// ---------------- sentence coefficients -------------------------------------
__global__ void coef_kernel(const int* __restrict__ nidx, const float* __restrict__ w,
                            const float* __restrict__ cA, const float* __restrict__ cB,
                            float* __restrict__ outA, float* __restrict__ outB) {
    const int b   = blockIdx.x;
    const int tid = threadIdx.x;
    const int NK  = S_ * KSEL;
    float accA[NB] = {}, accB[NB] = {};
    float ws = 0.f;
    for (int n = tid; n < NK; n += 256) {
        float wv = w[b * NK + n];
        int   id = nidx[b * NK + n];
        ws += wv;
        const float4* pa = (const float4*)(cA + (size_t)id * NB);
        const float4* pb = (const float4*)(cB + (size_t)id * NB);
#pragma unroll
        for (int q = 0; q < 4; q++) {
            float4 va = pa[q], vb = pb[q];
            accA[q*4+0] += wv * va.x; accA[q*4+1] += wv * va.y;
            accA[q*4+2] += wv * va.z; accA[q*4+3] += wv * va.w;
            accB[q*4+0] += wv * vb.x; accB[q*4+1] += wv * vb.y;
            accB[q*4+2] += wv * vb.z; accB[q*4+3] += wv * vb.w;
        }
    }
    __shared__ float sbuf[33][9];
    __shared__ float sfin[33];
    const int lane = tid & 31, wid = tid >> 5;
    auto wred = [](float v) {
#pragma unroll
        for (int o = 16; o > 0; o >>= 1) v += __shfl_down_sync(0xffffffffu, v, o);
        return v;
    };
    float r = wred(ws);
    if (lane == 0) sbuf[0][wid] = r;
#pragma unroll
    for (int i = 0; i < NB; i++) { float v = wred(accA[i]); if (lane == 0) sbuf[1 + i][wid] = v; }
#pragma unroll
    for (int i = 0; i < NB; i++) { float v = wred(accB[i]); if (lane == 0) sbuf[17 + i][wid] = v; }
    __syncthreads();
    if (tid < 33) {
        float s = 0.f;
#pragma unroll
        for (int j = 0; j < 8; j++) s += sbuf[tid][j];
        sfin[tid] = s;
    }
    __syncthreads();
    const float denom = sfin[0] + EPSN;
    if (tid < NB)            outA[b * NB + tid]        = sfin[1 + tid]  / denom;
    else if (tid < 2 * NB)   outB[b * NB + (tid - NB)] = sfin[17 + tid - NB] / denom;
}

// ================= merged prep kernel (grid-range dispatch) ==================
#define PR_TS0   0            // 16384 blocks : token_sig -> ts hi/lo
#define PR_XS0   16384        // 16384 blocks : x -> x hi/lo (elementwise)
#define PR_AT0   32768        // 128 blocks   : build AT hi/lo [b][r][d]
#define PR_BBT0  32896        // 512 blocks   : build BmT hi/lo [b][f][r]
#define PR_TDW0  33408        // 4096 blocks  : transpose+split down_w
#define PR_TW20  37504        // 1024 blocks  : transpose+split w2
#define PR_TW10  38528        // 256 blocks   : transpose+split w1
#define PR_END   38784

__device__ __forceinline__ void prep_transpose(const float* __restrict__ in,
                                               __nv_bfloat16* __restrict__ ohi,
                                               __nv_bfloat16* __restrict__ olo,
                                               int R, int C, int gx, int gy,
                                               float* tile /*[32][33]*/) {
    const int tid = threadIdx.x;
    const int tx = tid & 31, ty = tid >> 5;
    const int c0 = gx * 32, r0 = gy * 32;
#pragma unroll
    for (int j = 0; j < 32; j += 8)
        tile[(ty + j) * 33 + tx] = in[(size_t)(r0 + ty + j) * C + c0 + tx];
    __syncthreads();
#pragma unroll
    for (int j = 0; j < 32; j += 8) {
        float v = tile[tx * 33 + ty + j];
        size_t o = (size_t)(c0 + ty + j) * R + r0 + tx;
        __nv_bfloat16 h, l; split_bf16(v, h, l);
        ohi[o] = h; olo[o] = l;
    }
}

__global__ void __launch_bounds__(256)
prep_kernel(const float* __restrict__ x,
            const float* __restrict__ sel, const float* __restrict__ w,
            const float* __restrict__ basisA, const float* __restrict__ basisB,
            const float* __restrict__ w1, const float* __restrict__ w2,
            const float* __restrict__ dw) {
    __shared__ float tile[64 * 65];
    const int blk = blockIdx.x;
    const int tid = threadIdx.x;

    if (blk < PR_XS0) {
        int t = blk * 256 + tid;
        int d4 = t & 255;
        int bs = t >> 8;
        const float* base = sel + (size_t)bs * KSEL * DM + d4 * 4;
        const float* wp   = w + (size_t)bs * KSEL;
        float4 acc = make_float4(0, 0, 0, 0);
#pragma unroll
        for (int k = 0; k < KSEL; k++) {
            float  wv = wp[k];
            float4 v  = *(const float4*)(base + k * DM);
            acc.x += wv * v.x; acc.y += wv * v.y; acc.z += wv * v.z; acc.w += wv * v.w;
        }
        union { __nv_bfloat16 b[4]; uint2 u; } ph, pl;
        split_bf16(acc.x, ph.b[0], pl.b[0]);
        split_bf16(acc.y, ph.b[1], pl.b[1]);
        split_bf16(acc.z, ph.b[2], pl.b[2]);
        split_bf16(acc.w, ph.b[3], pl.b[3]);
        size_t o = (size_t)bs * DM + d4 * 4;
        *(uint2*)(g_tshi + o) = ph.u;
        *(uint2*)(g_tslo + o) = pl.u;
    } else if (blk < PR_AT0) {
        size_t t = (size_t)(blk - PR_XS0) * 256 + tid;
        size_t e = t * 4;
        float4 v = *(const float4*)(x + e);
        union { __nv_bfloat16 b[4]; uint2 u; } ph, pl;
        split_bf16(v.x, ph.b[0], pl.b[0]);
        split_bf16(v.y, ph.b[1], pl.b[1]);
        split_bf16(v.z, ph.b[2], pl.b[2]);
        split_bf16(v.w, ph.b[3], pl.b[3]);
        *(uint2*)(g_xhi + e) = ph.u;
        *(uint2*)(g_xlo + e) = pl.u;
    } else if (blk < PR_BBT0) {
        int lb = blk - PR_AT0;
        int b  = lb >> 4;
        int d0 = (lb & 15) * 64;
        int dl = tid >> 2;
        int rq = tid & 3;
        float accv[16];
#pragma unroll
        for (int j = 0; j < 16; j++) accv[j] = 0.f;
#pragma unroll
        for (int i = 0; i < NB; i++) {
            float c = g_coefA[b * NB + i];
            const float* src = basisA + ((size_t)i * DM + d0 + dl) * RANK + rq * 16;
#pragma unroll
            for (int q = 0; q < 4; q++) {
                float4 v = *(const float4*)(src + q * 4);
                accv[q*4+0] += c * v.x; accv[q*4+1] += c * v.y;
                accv[q*4+2] += c * v.z; accv[q*4+3] += c * v.w;
            }
        }
#pragma unroll
        for (int j = 0; j < 16; j++) tile[dl * 65 + rq * 16 + j] = accv[j];
        __syncthreads();
        int r  = tid >> 2;
        int dq = tid & 3;
        size_t obase = ((size_t)b * RANK + r) * DM + d0 + dq * 16;
        __nv_bfloat16 hv[16], lv[16];
#pragma unroll
        for (int j = 0; j < 16; j++) {
            float v = tile[(dq * 16 + j) * 65 + r];
            split_bf16(v, hv[j], lv[j]);
        }
#pragma unroll
        for (int j = 0; j < 16; j += 8) {
            *(uint4*)(g_AThi + obase + j) = *(uint4*)(hv + j);
            *(uint4*)(g_ATlo + obase + j) = *(uint4*)(lv + j);
        }
    } else if (blk < PR_TDW0) {
        int lb = blk - PR_BBT0;
        int f0 = (lb & 63) * 64;
        int b  = lb >> 6;
        int r  = tid >> 2;
        int fq = tid & 3;
        float accv[16];
#pragma unroll
        for (int j = 0; j < 16; j++) accv[j] = 0.f;
#pragma unroll
        for (int i = 0; i < NB; i++) {
            float c = g_coefB[b * NB + i];
            const float* src = basisB + ((size_t)i * RANK + r) * DFF + f0 + fq * 16;
#pragma unroll
            for (int q = 0; q < 4; q++) {
                float4 v = *(const float4*)(src + q * 4);
                accv[q*4+0] += c * v.x; accv[q*4+1] += c * v.y;
                accv[q*4+2] += c * v.z; accv[q*4+3] += c * v.w;
            }
        }
#pragma unroll
        for (int j = 0; j < 16; j++) tile[r * 65 + fq * 16 + j] = accv[j];
        __syncthreads();
        int f  = tid >> 2;
        int rq2 = tid & 3;
        size_t obase = ((size_t)b * DFF + f0 + f) * RANK + rq2 * 16;
        __nv_bfloat16 hv[16], lv[16];
#pragma unroll
        for (int j = 0; j < 16; j++) {
            float v = tile[(rq2 * 16 + j) * 65 + f];
            split_bf16(v, hv[j], lv[j]);
        }
#pragma unroll
        for (int j = 0; j < 16; j += 8) {
            *(uint4*)(g_BmThi + obase + j) = *(uint4*)(hv + j);
            *(uint4*)(g_BmTlo + obase + j) = *(uint4*)(lv + j);
        }
    } else if (blk < PR_TW20) {
        int lb = blk - PR_TDW0;
        prep_transpose(dw, g_dwThi, g_dwTlo, DFF, DM, lb & 31, lb >> 5, tile);
    } else if (blk < PR_TW10) {
        int lb = blk - PR_TW20;
        prep_transpose(w2, g_w2Thi, g_w2Tlo, TRH, DFF, lb & 127, lb >> 7, tile);
    } else {
        int lb = blk - PR_TW10;
        prep_transpose(w1, g_w1Thi, g_w1Tlo, DM, TRH, lb & 7, lb >> 3, tile);
    }
}

// ---------------- launch -----------------------------------------------------
extern "C" void kernel_launch(void* const* d_in, const int* in_sizes, int n_in,
                              void* d_out, int out_size) {
    (void)in_sizes; (void)n_in; (void)out_size;
    const float* x    = (const float*)d_in[0];
    const float* sel  = (const float*)d_in[1];
    const int*   nidx = (const int*)  d_in[2];
    const float* nw   = (const float*)d_in[3];
    const float* bA   = (const float*)d_in[4];
    const float* bB   = (const float*)d_in[5];
    const float* cA   = (const float*)d_in[6];
    const float* cB   = (const float*)d_in[7];
    const float* w1   = (const float*)d_in[8];
    const float* b1   = (const float*)d_in[9];
    const float* w2   = (const float*)d_in[10];
    const float* b2   = (const float*)d_in[11];
    const float* dw   = (const float*)d_in[12];
    const float* db   = (const float*)d_in[13];
    float* out = (float*)d_out;

    float *pCA, *pCB;
    cudaGetSymbolAddress((void**)&pCA, g_coefA);
    cudaGetSymbolAddress((void**)&pCB, g_coefB);

    cudaFuncSetAttribute(gemm45_kernel,  cudaFuncAttributeMaxDynamicSharedMemorySize, SM4);
    cudaFuncSetAttribute(fused67_kernel, cudaFuncAttributeMaxDynamicSharedMemorySize, SM8);
    cudaFuncSetAttribute(gemm8_kernel,   cudaFuncAttributeMaxDynamicSharedMemorySize, SM8);

    // 0. sentence coefficients
    coef_kernel<<<B_, 256>>>(nidx, nw, cA, cB, pCA, pCB);
    // 1. prep: token_sig + x-split + AT + BmT + weight transposes
    prep_kernel<<<PR_END, 256>>>(x, sel, nw, bA, bB, w1, w2, dw);
    // 2. combined gemm4+gemm5 (U and P), K=1024
    {
        dim3 grid(5, BS_ / 128);
        gemm45_kernel<<<grid, 256, SM4>>>(b1);
    }
    // 3. fused gemm6+gemm7: Hsplit = gelu(P@BmT[b]) + 0.1*(U@w2 + b2) — PROFILED
    {
        dim3 grid(DFF / 128, BS_ / 128);
        fused67_kernel<<<grid, 256, SM8>>>(b2);
    }
    // 4. out = Hsplit @ down_w + db   (M=16384 N=1024 K=4096 — dominant)
    {
        dim3 grid(DM / 128, BS_ / 128);
        gemm8_kernel<<<grid, 256, SM8>>>(out, db);
    }
}